// round 15
// baseline (speedup 1.0000x reference)
#include <cuda_runtime.h>
#include <cuda_bf16.h>
#include <cstdint>

#define Bn 2
#define Sn 2048
#define Dn 1024
#define Hn 16
#define HDn 64
#define BHn (Bn*Hn)
#define Mn (Bn*Sn)       // 4096
#define KSEL 1024        // top-k count

// ---- scratch (static device allocations; no cudaMalloc allowed) ----
__device__ float g_Q[Bn*Hn*Sn*HDn];   // (b,h,s,hd)
__device__ float g_K[Bn*Hn*Sn*HDn];
__device__ float g_V[Bn*Hn*Sn*HDn];
__device__ float g_AV[Bn*Hn*Sn*HDn];

// order-preserving float->uint key
__device__ __forceinline__ unsigned fkey(float f){
    unsigned uf = __float_as_uint(f);
    return (uf & 0x80000000u) ? ~uf : (uf | 0x80000000u);
}
__device__ __forceinline__ float finv(unsigned k){
    return __uint_as_float((k & 0x80000000u) ? (k & 0x7FFFFFFFu) : ~k);
}

// ---- tf32 helpers ----
__device__ __forceinline__ void tf32split(float x, unsigned &hi, unsigned &lo){
    unsigned h; asm("cvt.rna.tf32.f32 %0, %1;" : "=r"(h) : "f"(x));
    float hf = __uint_as_float(h);
    asm("cvt.rna.tf32.f32 %0, %1;" : "=r"(lo) : "f"(x - hf));
    hi = h;
}
__device__ __forceinline__ void split4(float4 v, uint4 &hi, uint4 &lo){
    tf32split(v.x, hi.x, lo.x);
    tf32split(v.y, hi.y, lo.y);
    tf32split(v.z, hi.z, lo.z);
    tf32split(v.w, hi.w, lo.w);
}
__device__ __forceinline__ void mma_tf32(float* c, const unsigned* a, const unsigned* b){
    asm volatile("mma.sync.aligned.m16n8k8.row.col.f32.tf32.tf32.f32 "
        "{%0,%1,%2,%3}, {%4,%5,%6,%7}, {%8,%9}, {%0,%1,%2,%3};"
        : "+f"(c[0]), "+f"(c[1]), "+f"(c[2]), "+f"(c[3])
        : "r"(a[0]), "r"(a[1]), "r"(a[2]), "r"(a[3]), "r"(b[0]), "r"(b[1]));
}

// ---- bf16x3 helpers (linear-path GEMMs) ----
__device__ __forceinline__ void bf16x2split(float x, float y, unsigned &hi, unsigned &lo){
    __nv_bfloat16 xh = __float2bfloat16_rn(x);
    __nv_bfloat16 yh = __float2bfloat16_rn(y);
    float xr = x - __bfloat162float(xh);
    float yr = y - __bfloat162float(yh);
    __nv_bfloat16 xl = __float2bfloat16_rn(xr);
    __nv_bfloat16 yl = __float2bfloat16_rn(yr);
    hi = (unsigned)__bfloat16_as_ushort(xh) | ((unsigned)__bfloat16_as_ushort(yh) << 16);
    lo = (unsigned)__bfloat16_as_ushort(xl) | ((unsigned)__bfloat16_as_ushort(yl) << 16);
}
__device__ __forceinline__ void mma_bf16(float* c, const unsigned* a, const unsigned* b){
    asm volatile("mma.sync.aligned.m16n8k16.row.col.f32.bf16.bf16.f32 "
        "{%0,%1,%2,%3}, {%4,%5,%6,%7}, {%8,%9}, {%0,%1,%2,%3};"
        : "+f"(c[0]), "+f"(c[1]), "+f"(c[2]), "+f"(c[3])
        : "r"(a[0]), "r"(a[1]), "r"(a[2]), "r"(a[3]), "r"(b[0]), "r"(b[1]));
}

// tile strides (u32 words)
#define TSA 68   // tf32 64-wide row tiles: conflict-free fragment LDS
#define TS3 36   // bf16 32-word row tiles: conflict-free
#define TSV 72   // bf16 av V pair-row tiles: conflict-free
#define SROW 2052 // fused kernel score-row stride (words): float4-aligned, <=2-way STS

// tf32x3 warp micro (DUAL accumulators) for QK proj
__device__ __forceinline__ void mma_chunk_rowB_dual(
    float accH[2][4][4], float accX[2][4][4],
    const unsigned* Ah, const unsigned* Al,
    const unsigned* Bh, const unsigned* Bl, int mb, int nb, int g, int c)
{
    #pragma unroll
    for (int ks = 0; ks < 8; ks++){
        unsigned ah[2][4], al[2][4];
        #pragma unroll
        for (int mf=0; mf<2; mf++){
            const unsigned* bse = Ah + (mb+mf*16)*TSA + ks*8;
            const unsigned* bsl = Al + (mb+mf*16)*TSA + ks*8;
            ah[mf][0]=bse[ g   *TSA + c  ]; al[mf][0]=bsl[ g   *TSA + c  ];
            ah[mf][1]=bse[(g+8)*TSA + c  ]; al[mf][1]=bsl[(g+8)*TSA + c  ];
            ah[mf][2]=bse[ g   *TSA + c+4]; al[mf][2]=bsl[ g   *TSA + c+4];
            ah[mf][3]=bse[(g+8)*TSA + c+4]; al[mf][3]=bsl[(g+8)*TSA + c+4];
        }
        #pragma unroll
        for (int nf=0; nf<4; nf++){
            unsigned bh_[2], bl_[2];
            const unsigned* bse = Bh + (nb+nf*8+g)*TSA + ks*8;
            const unsigned* bsl = Bl + (nb+nf*8+g)*TSA + ks*8;
            bh_[0]=bse[c]; bh_[1]=bse[c+4];
            bl_[0]=bsl[c]; bl_[1]=bsl[c+4];
            #pragma unroll
            for (int mf=0; mf<2; mf++){
                mma_tf32(accH[mf][nf], ah[mf], bh_);
                mma_tf32(accX[mf][nf], ah[mf], bl_);
                mma_tf32(accX[mf][nf], al[mf], bh_);
            }
        }
    }
}

// bf16x3 warp micro: 32m x 32n, one 64-k chunk
__device__ __forceinline__ void mma_chunk_rowB_bf16(
    float acc[2][4][4], const unsigned* Ah, const unsigned* Al,
    const unsigned* Bh, const unsigned* Bl, int mb, int nb, int g, int c)
{
    #pragma unroll
    for (int ks = 0; ks < 4; ks++){
        unsigned ah[2][4], al[2][4];
        #pragma unroll
        for (int mf=0; mf<2; mf++){
            const unsigned* ph = Ah + (mb+mf*16)*TS3 + ks*8;
            const unsigned* pl = Al + (mb+mf*16)*TS3 + ks*8;
            ah[mf][0]=ph[ g   *TS3 + c  ]; al[mf][0]=pl[ g   *TS3 + c  ];
            ah[mf][1]=ph[(g+8)*TS3 + c  ]; al[mf][1]=pl[(g+8)*TS3 + c  ];
            ah[mf][2]=ph[ g   *TS3 + c+4]; al[mf][2]=pl[ g   *TS3 + c+4];
            ah[mf][3]=ph[(g+8)*TS3 + c+4]; al[mf][3]=pl[(g+8)*TS3 + c+4];
        }
        #pragma unroll
        for (int nf=0; nf<4; nf++){
            const unsigned* ph = Bh + (nb+nf*8+g)*TS3 + ks*8;
            const unsigned* pl = Bl + (nb+nf*8+g)*TS3 + ks*8;
            unsigned bh_[2] = { ph[c], ph[c+4] };
            unsigned bl_[2] = { pl[c], pl[c+4] };
            #pragma unroll
            for (int mf=0; mf<2; mf++){
                mma_bf16(acc[mf][nf], ah[mf], bh_);
                mma_bf16(acc[mf][nf], ah[mf], bl_);
                mma_bf16(acc[mf][nf], al[mf], bh_);
            }
        }
    }
}

// ============================================================
// Kernel 1a: Q/K projections via tf32x3 DUAL-ACC MMA (R14 proven)
// ============================================================
__global__ __launch_bounds__(256) void projqk_tf32d_kernel(
    const float* __restrict__ Aq, const float* __restrict__ Ak,
    const float* __restrict__ Wq, const float* __restrict__ Wk,
    const float* __restrict__ bq, const float* __restrict__ bk,
    float* __restrict__ Oq, float* __restrict__ Ok)
{
    const float* A; const float* W; const float* bias; float* Out;
    if (blockIdx.z == 0) { A = Aq; W = Wq; bias = bq; Out = Oq; }
    else                 { A = Ak; W = Wk; bias = bk; Out = Ok; }

    extern __shared__ unsigned sm[];
    unsigned* Ah = sm;
    unsigned* Al = Ah + 128*TSA;
    unsigned* Bh = Al + 128*TSA;
    unsigned* Bl = Bh + 64*TSA;

    int m0 = blockIdx.y * 128;
    int n0 = blockIdx.x * 64;
    int tid = threadIdx.x;
    int lane = tid & 31, w = tid >> 5;
    int mb = (w >> 1) * 32, nb = (w & 1) * 32;
    int g = lane >> 2, c = lane & 3;

    float accH[2][4][4], accX[2][4][4];
    #pragma unroll
    for (int mf=0;mf<2;mf++)
        #pragma unroll
        for (int nf=0;nf<4;nf++)
            #pragma unroll
            for (int e=0;e<4;e++){ accH[mf][nf][e]=0.f; accX[mf][nf][e]=0.f; }

    for (int k0 = 0; k0 < Dn; k0 += 64) {
        #pragma unroll
        for (int i = 0; i < 8; i++){
            int idx = tid + i*256;
            int r = idx >> 4, c4 = idx & 15;
            float4 v = *(const float4*)(A + (size_t)(m0+r)*Dn + k0 + c4*4);
            uint4 hi, lo; split4(v, hi, lo);
            *(uint4*)&Ah[r*TSA + c4*4] = hi;
            *(uint4*)&Al[r*TSA + c4*4] = lo;
        }
        #pragma unroll
        for (int i = 0; i < 4; i++){
            int idx = tid + i*256;
            int r = idx >> 4, c4 = idx & 15;
            float4 v = *(const float4*)(W + (size_t)(n0+r)*Dn + k0 + c4*4);
            uint4 hi, lo; split4(v, hi, lo);
            *(uint4*)&Bh[r*TSA + c4*4] = hi;
            *(uint4*)&Bl[r*TSA + c4*4] = lo;
        }
        __syncthreads();
        mma_chunk_rowB_dual(accH, accX, Ah, Al, Bh, Bl, mb, nb, g, c);
        __syncthreads();
    }

    #pragma unroll
    for (int mf=0; mf<2; mf++){
        #pragma unroll
        for (int nf=0; nf<4; nf++){
            int col = n0 + nb + nf*8 + 2*c;
            int h = col >> 6, hd = col & 63;
            float b0 = bias[col], b1 = bias[col+1];
            #pragma unroll
            for (int rr = 0; rr < 2; rr++){
                int row = m0 + mb + mf*16 + g + rr*8;
                int b = row / Sn, s = row % Sn;
                float2 v = make_float2(
                    (accH[mf][nf][2*rr]   + accX[mf][nf][2*rr])   + b0,
                    (accH[mf][nf][2*rr+1] + accX[mf][nf][2*rr+1]) + b1);
                *(float2*)&Out[(((size_t)(b*Hn + h))*Sn + s)*HDn + hd] = v;
            }
        }
    }
}

// ============================================================
// Kernel 1b: V projection via bf16x3 MMA (R13 proven)
// ============================================================
__global__ __launch_bounds__(256) void projv_bf16_kernel(
    const float* __restrict__ A, const float* __restrict__ W,
    const float* __restrict__ bias, float* __restrict__ Out)
{
    extern __shared__ unsigned sm[];
    unsigned* Ah = sm;
    unsigned* Al = Ah + 128*TS3;
    unsigned* Bh = Al + 128*TS3;
    unsigned* Bl = Bh + 64*TS3;

    int m0 = blockIdx.y * 128;
    int n0 = blockIdx.x * 64;
    int tid = threadIdx.x;
    int lane = tid & 31, w = tid >> 5;
    int mb = (w >> 1) * 32, nb = (w & 1) * 32;
    int g = lane >> 2, c = lane & 3;

    float acc[2][4][4];
    #pragma unroll
    for (int mf=0;mf<2;mf++)
        #pragma unroll
        for (int nf=0;nf<4;nf++)
            #pragma unroll
            for (int e=0;e<4;e++) acc[mf][nf][e]=0.f;

    for (int k0 = 0; k0 < Dn; k0 += 64) {
        #pragma unroll
        for (int i = 0; i < 8; i++){
            int idx = tid + i*256;
            int r = idx >> 4, c4 = idx & 15;
            float4 v = *(const float4*)(A + (size_t)(m0+r)*Dn + k0 + c4*4);
            unsigned h0,l0,h1,l1;
            bf16x2split(v.x, v.y, h0, l0);
            bf16x2split(v.z, v.w, h1, l1);
            *(uint2*)&Ah[r*TS3 + c4*2] = make_uint2(h0, h1);
            *(uint2*)&Al[r*TS3 + c4*2] = make_uint2(l0, l1);
        }
        #pragma unroll
        for (int i = 0; i < 4; i++){
            int idx = tid + i*256;
            int r = idx >> 4, c4 = idx & 15;
            float4 v = *(const float4*)(W + (size_t)(n0+r)*Dn + k0 + c4*4);
            unsigned h0,l0,h1,l1;
            bf16x2split(v.x, v.y, h0, l0);
            bf16x2split(v.z, v.w, h1, l1);
            *(uint2*)&Bh[r*TS3 + c4*2] = make_uint2(h0, h1);
            *(uint2*)&Bl[r*TS3 + c4*2] = make_uint2(l0, l1);
        }
        __syncthreads();
        mma_chunk_rowB_bf16(acc, Ah, Al, Bh, Bl, mb, nb, g, c);
        __syncthreads();
    }

    #pragma unroll
    for (int mf=0; mf<2; mf++){
        #pragma unroll
        for (int nf=0; nf<4; nf++){
            int col = n0 + nb + nf*8 + 2*c;
            int h = col >> 6, hd = col & 63;
            float b0 = bias[col], b1 = bias[col+1];
            #pragma unroll
            for (int rr = 0; rr < 2; rr++){
                int row = m0 + mb + mf*16 + g + rr*8;
                int b = row / Sn, s = row % Sn;
                float2 v = make_float2(acc[mf][nf][2*rr] + b0, acc[mf][nf][2*rr+1] + b1);
                *(float2*)&Out[(((size_t)(b*Hn + h))*Sn + s)*HDn + hd] = v;
            }
        }
    }
}

// ============================================================
// Kernel 2: FUSED scores (tf32x3, bit-identical to R11/R14 scores) +
// exact per-warp top-k radix select + softmax. Block: 16 q-rows x 2048 k.
// 512 threads (16 warps). Scores stay in smem; only the final normalized
// attn row is written to global (saves a full 537MB write + 537MB read).
// smem: S[16][SROW] + Qh/Ql[16][TSA] + Kh/Kl[128][TSA]; hist aliases Kh.
// ============================================================
#define FUSED_SMEM ((16*SROW + 2*16*TSA + 2*128*TSA) * 4)
__global__ __launch_bounds__(512) void fused_scores_topk_kernel(float* __restrict__ attn)
{
    extern __shared__ unsigned sm[];
    float*    S  = (float*)sm;           // 16*SROW
    unsigned* Qh = sm + 16*SROW;         // 16*TSA
    unsigned* Ql = Qh + 16*TSA;
    unsigned* Kh = Ql + 16*TSA;          // 128*TSA
    unsigned* Kl = Kh + 128*TSA;

    int bh = blockIdx.y;
    int q0 = blockIdx.x * 16;
    const float* Qb = g_Q + (size_t)bh*Sn*HDn;
    const float* Kb = g_K + (size_t)bh*Sn*HDn;

    int tid = threadIdx.x;
    int lane = tid & 31, w = tid >> 5;   // w 0..15
    int g = lane >> 2, c = lane & 3;

    // ---- load Q tile 16x64 (hi/lo split) ----
    if (tid < 256) {
        int r = tid >> 4, c4 = tid & 15;
        float4 v = *(const float4*)(Qb + (size_t)(q0+r)*HDn + c4*4);
        uint4 hi, lo; split4(v, hi, lo);
        *(uint4*)&Qh[r*TSA + c4*4] = hi;
        *(uint4*)&Ql[r*TSA + c4*4] = lo;
    }
    __syncthreads();

    // ---- phase 1: scores, 16 chunks of 128 k; warp w owns n-frag w ----
    const float scale = 0.125f;
    for (int cc = 0; cc < 16; cc++) {
        int kbase = cc * 128;
        #pragma unroll
        for (int i = 0; i < 4; i++){
            int idx = tid + i*512;           // 0..2047
            int r = idx >> 4, c4 = idx & 15; // r 0..127
            float4 v = *(const float4*)(Kb + (size_t)(kbase+r)*HDn + c4*4);
            uint4 hi, lo; split4(v, hi, lo);
            *(uint4*)&Kh[r*TSA + c4*4] = hi;
            *(uint4*)&Kl[r*TSA + c4*4] = lo;
        }
        __syncthreads();

        float acc[4] = {0.f, 0.f, 0.f, 0.f};
        #pragma unroll
        for (int ks = 0; ks < 8; ks++){
            unsigned ah[4], al[4];
            const unsigned* ph = Qh + ks*8;
            const unsigned* pl = Ql + ks*8;
            ah[0]=ph[ g   *TSA + c  ]; al[0]=pl[ g   *TSA + c  ];
            ah[1]=ph[(g+8)*TSA + c  ]; al[1]=pl[(g+8)*TSA + c  ];
            ah[2]=ph[ g   *TSA + c+4]; al[2]=pl[ g   *TSA + c+4];
            ah[3]=ph[(g+8)*TSA + c+4]; al[3]=pl[(g+8)*TSA + c+4];
            const unsigned* qh2 = Kh + (w*8+g)*TSA + ks*8;
            const unsigned* ql2 = Kl + (w*8+g)*TSA + ks*8;
            unsigned bh_[2] = { qh2[c], qh2[c+4] };
            unsigned bl_[2] = { ql2[c], ql2[c+4] };
            mma_tf32(acc, ah, bh_);   // hh
            mma_tf32(acc, ah, bl_);   // hl
            mma_tf32(acc, al, bh_);   // lh
        }
        int col = kbase + w*8 + 2*c;
        *(float2*)&S[ g    *SROW + col] = make_float2(acc[0]*scale, acc[1]*scale);
        *(float2*)&S[(g+8) *SROW + col] = make_float2(acc[2]*scale, acc[3]*scale);
        __syncthreads();
    }

    // ---- phase 2: per-warp top-k + softmax on row w (hist aliases Kh) ----
    unsigned* H = Kh + w*(32*33);
    const float* rowp = S + w*SROW;
    float* arow = attn + ((size_t)bh*Sn + (q0 + w))*Sn;

    unsigned ku[64];
    #pragma unroll
    for (int j = 0; j < 16; j++) {
        float4 v = *(const float4*)(rowp + lane*4 + j*128);
        ku[j*4+0]=fkey(v.x); ku[j*4+1]=fkey(v.y); ku[j*4+2]=fkey(v.z); ku[j*4+3]=fkey(v.w);
    }
    unsigned kmax = 0u;
    #pragma unroll
    for (int e = 0; e < 64; e++) kmax = max(kmax, ku[e]);
    #pragma unroll
    for (int o=16;o>0;o>>=1) kmax = max(kmax, __shfl_xor_sync(0xffffffffu, kmax, o));
    float gmax = finv(kmax);

    unsigned prefix = 0u;
    int r = KSEL;
    #pragma unroll 1
    for (int p = 0; p < 6; p++) {
        const int shift = (p < 5) ? (26 - 6*p) : 0;
        const int nbit  = (p < 5) ? 6 : 2;
        const unsigned binmask = (1u << nbit) - 1u;
        const int sh2 = shift + nbit;
        const unsigned hm = (sh2 >= 32) ? 0u : (0xFFFFFFFFu << sh2);

        unsigned* reg = H + lane*33;
        #pragma unroll
        for (int i = 0; i < 33; i++) reg[i] = 0u;
        __syncwarp();
        #pragma unroll
        for (int e = 0; e < 64; e++) {
            unsigned u = ku[e];
            if ((u & hm) == prefix) {
                unsigned b = (u >> shift) & binmask;
                atomicAdd(&H[lane*33 + (b >> 1)], 1u << (16*(b & 1)));
            }
        }
        __syncwarp();
        unsigned acc = 0u;
        #pragma unroll
        for (int l = 0; l < 32; l++) acc += H[l*33 + lane];
        int cLo = (int)(acc & 0xFFFFu);
        int cHi = (int)(acc >> 16);
        int s   = cLo + cHi;
        int suf = s;
        #pragma unroll
        for (int o = 1; o < 32; o <<= 1) {
            int v = __shfl_down_sync(0xffffffffu, suf, o);
            if (lane + o < 32) suf += v;
        }
        int geL = suf;
        int geH = suf - cLo;
        int geN = suf - s;
        int found = -1, rnew = 0;
        if (geH >= r && geN < r) { found = 2*lane + 1; rnew = r - geN; }
        if (geL >= r && geH < r) { found = 2*lane;     rnew = r - geH; }
        unsigned ball = __ballot_sync(0xffffffffu, found >= 0);
        int src = __ffs(ball) - 1;
        unsigned bsel = __shfl_sync(0xffffffffu, (unsigned)found, src);
        r = __shfl_sync(0xffffffffu, rnew, src);
        prefix |= (bsel << shift);
        __syncwarp();
    }
    unsigned thr = prefix;

    float lsumf = 0.f;
    #pragma unroll
    for (int e = 0; e < 64; e++) {
        unsigned k = ku[e];
        float ex = 0.f;
        if (k >= thr) ex = __expf(finv(k) - gmax);
        ku[e] = __float_as_uint(ex);
        lsumf += ex;
    }
    #pragma unroll
    for (int o=16;o>0;o>>=1) lsumf += __shfl_xor_sync(0xffffffffu, lsumf, o);
    float inv = 1.f / lsumf;
    #pragma unroll
    for (int j = 0; j < 16; j++) {
        float4 v = make_float4(__uint_as_float(ku[j*4+0])*inv,
                               __uint_as_float(ku[j*4+1])*inv,
                               __uint_as_float(ku[j*4+2])*inv,
                               __uint_as_float(ku[j*4+3])*inv);
        *(float4*)(arow + lane*4 + j*128) = v;
    }
}

// ============================================================
// Kernel 4: AV via bf16x3 MMA (R13 proven)
// ============================================================
__global__ __launch_bounds__(256) void av_bf16_kernel(const float* __restrict__ attn)
{
    extern __shared__ unsigned sm[];
    unsigned* Ah = sm;
    unsigned* Al = Ah + 128*TS3;
    unsigned* Vh = Al + 128*TS3;
    unsigned* Vl = Vh + 32*TSV;

    int bh = blockIdx.y;
    int m0 = blockIdx.x * 128;
    const float* Ab = attn + (size_t)bh*Sn*Sn;
    const float* Vb = g_V + (size_t)bh*Sn*HDn;
    float* Cb = g_AV + (size_t)bh*Sn*HDn;
    int tid = threadIdx.x;
    int lane = tid & 31, w = tid >> 5;
    int mb = (w >> 1) * 32, nb = (w & 1) * 32;
    int g = lane >> 2, c = lane & 3;

    float acc[2][4][4];
    #pragma unroll
    for (int mf=0;mf<2;mf++)
        #pragma unroll
        for (int nf=0;nf<4;nf++)
            #pragma unroll
            for (int e=0;e<4;e++) acc[mf][nf][e]=0.f;

    for (int k0 = 0; k0 < Sn; k0 += 64) {
        #pragma unroll
        for (int i = 0; i < 8; i++){
            int idx = tid + i*256;
            int r = idx >> 4, c4 = idx & 15;
            float4 v = *(const float4*)(Ab + (size_t)(m0+r)*Sn + k0 + c4*4);
            unsigned h0,l0,h1,l1;
            bf16x2split(v.x, v.y, h0, l0);
            bf16x2split(v.z, v.w, h1, l1);
            *(uint2*)&Ah[r*TS3 + c4*2] = make_uint2(h0, h1);
            *(uint2*)&Al[r*TS3 + c4*2] = make_uint2(l0, l1);
        }
        #pragma unroll
        for (int i = 0; i < 2; i++){
            int idx = tid + i*256;
            int pr = idx >> 4, c4 = idx & 15;
            int d = c4 * 4;
            float4 v0 = *(const float4*)(Vb + (size_t)(k0 + 2*pr    )*HDn + d);
            float4 v1 = *(const float4*)(Vb + (size_t)(k0 + 2*pr + 1)*HDn + d);
            unsigned h, l;
            bf16x2split(v0.x, v1.x, h, l); Vh[pr*TSV + d + 0] = h; Vl[pr*TSV + d + 0] = l;
            bf16x2split(v0.y, v1.y, h, l); Vh[pr*TSV + d + 1] = h; Vl[pr*TSV + d + 1] = l;
            bf16x2split(v0.z, v1.z, h, l); Vh[pr*TSV + d + 2] = h; Vl[pr*TSV + d + 2] = l;
            bf16x2split(v0.w, v1.w, h, l); Vh[pr*TSV + d + 3] = h; Vl[pr*TSV + d + 3] = l;
        }
        __syncthreads();

        #pragma unroll
        for (int ks = 0; ks < 4; ks++){
            unsigned ah[2][4], al[2][4];
            #pragma unroll
            for (int mf=0; mf<2; mf++){
                const unsigned* ph = Ah + (mb+mf*16)*TS3 + ks*8;
                const unsigned* pl = Al + (mb+mf*16)*TS3 + ks*8;
                ah[mf][0]=ph[ g   *TS3 + c  ]; al[mf][0]=pl[ g   *TS3 + c  ];
                ah[mf][1]=ph[(g+8)*TS3 + c  ]; al[mf][1]=pl[(g+8)*TS3 + c  ];
                ah[mf][2]=ph[ g   *TS3 + c+4]; al[mf][2]=pl[ g   *TS3 + c+4];
                ah[mf][3]=ph[(g+8)*TS3 + c+4]; al[mf][3]=pl[(g+8)*TS3 + c+4];
            }
            #pragma unroll
            for (int nf=0; nf<4; nf++){
                int d = nb + nf*8 + g;
                unsigned bh_[2], bl_[2];
                bh_[0]=Vh[(ks*8 + c    )*TSV + d]; bl_[0]=Vl[(ks*8 + c    )*TSV + d];
                bh_[1]=Vh[(ks*8 + c + 4)*TSV + d]; bl_[1]=Vl[(ks*8 + c + 4)*TSV + d];
                #pragma unroll
                for (int mf=0; mf<2; mf++){
                    mma_bf16(acc[mf][nf], ah[mf], bh_);
                    mma_bf16(acc[mf][nf], ah[mf], bl_);
                    mma_bf16(acc[mf][nf], al[mf], bh_);
                }
            }
        }
        __syncthreads();
    }

    #pragma unroll
    for (int mf=0; mf<2; mf++){
        #pragma unroll
        for (int nf=0; nf<4; nf++){
            int col = nb + nf*8 + 2*c;
            #pragma unroll
            for (int rr = 0; rr < 2; rr++){
                int row = m0 + mb + mf*16 + g + rr*8;
                float2 v = make_float2(acc[mf][nf][2*rr], acc[mf][nf][2*rr+1]);
                *(float2*)(Cb + (size_t)row*HDn + col) = v;
            }
        }
    }
}

// ============================================================
// Kernel 5: out projection via bf16x3 MMA (R13 proven)
// ============================================================
__global__ __launch_bounds__(256) void outproj_bf16_kernel(
    const float* __restrict__ Wo, const float* __restrict__ bo,
    float* __restrict__ out)
{
    extern __shared__ unsigned sm[];
    unsigned* Ah = sm;
    unsigned* Al = Ah + 128*TS3;
    unsigned* Bh = Al + 128*TS3;
    unsigned* Bl = Bh + 64*TS3;

    int m0 = blockIdx.y * 128;
    int n0 = blockIdx.x * 64;
    int tid = threadIdx.x;
    int lane = tid & 31, w = tid >> 5;
    int mb = (w >> 1) * 32, nb = (w & 1) * 32;
    int g = lane >> 2, c = lane & 3;

    float acc[2][4][4];
    #pragma unroll
    for (int mf=0;mf<2;mf++)
        #pragma unroll
        for (int nf=0;nf<4;nf++)
            #pragma unroll
            for (int e=0;e<4;e++) acc[mf][nf][e]=0.f;

    for (int k0 = 0; k0 < Dn; k0 += 64) {
        int h = k0 >> 6;
        #pragma unroll
        for (int i = 0; i < 8; i++){
            int idx = tid + i*256;
            int r = idx >> 4, c4 = idx & 15;
            int m = m0 + r;
            int b = m / Sn, s = m % Sn;
            float4 v = *(const float4*)(g_AV + (((size_t)(b*Hn + h))*Sn + s)*HDn + c4*4);
            unsigned h0,l0,h1,l1;
            bf16x2split(v.x, v.y, h0, l0);
            bf16x2split(v.z, v.w, h1, l1);
            *(uint2*)&Ah[r*TS3 + c4*2] = make_uint2(h0, h1);
            *(uint2*)&Al[r*TS3 + c4*2] = make_uint2(l0, l1);
        }
        #pragma unroll
        for (int i = 0; i < 4; i++){
            int idx = tid + i*256;
            int r = idx >> 4, c4 = idx & 15;
            float4 v = *(const float4*)(Wo + (size_t)(n0+r)*Dn + k0 + c4*4);
            unsigned h0,l0,h1,l1;
            bf16x2split(v.x, v.y, h0, l0);
            bf16x2split(v.z, v.w, h1, l1);
            *(uint2*)&Bh[r*TS3 + c4*2] = make_uint2(h0, h1);
            *(uint2*)&Bl[r*TS3 + c4*2] = make_uint2(l0, l1);
        }
        __syncthreads();
        mma_chunk_rowB_bf16(acc, Ah, Al, Bh, Bl, mb, nb, g, c);
        __syncthreads();
    }

    #pragma unroll
    for (int mf=0; mf<2; mf++){
        #pragma unroll
        for (int nf=0; nf<4; nf++){
            int col = n0 + nb + nf*8 + 2*c;
            float b0 = bo[col], b1 = bo[col+1];
            #pragma unroll
            for (int rr = 0; rr < 2; rr++){
                int row = m0 + mb + mf*16 + g + rr*8;
                float2 v = make_float2(acc[mf][nf][2*rr] + b0, acc[mf][nf][2*rr+1] + b1);
                *(float2*)(out + (size_t)row*Dn + col) = v;
            }
        }
    }
}

// ============================================================
extern "C" void kernel_launch(void* const* d_in, const int* in_sizes, int n_in,
                              void* d_out, int out_size)
{
    const float* query = (const float*)d_in[0];
    const float* key   = (const float*)d_in[1];
    const float* value = (const float*)d_in[2];
    const float* Wq = (const float*)d_in[3];
    const float* bq = (const float*)d_in[4];
    const float* Wk = (const float*)d_in[5];
    const float* bk = (const float*)d_in[6];
    const float* Wv = (const float*)d_in[7];
    const float* bv = (const float*)d_in[8];
    const float* Wo = (const float*)d_in[9];
    const float* bo = (const float*)d_in[10];

    float* out  = (float*)d_out;
    float* attn = out + (size_t)Bn * Sn * Dn;

    float* gQ;  cudaGetSymbolAddress((void**)&gQ,  g_Q);
    float* gK;  cudaGetSymbolAddress((void**)&gK,  g_K);
    float* gV;  cudaGetSymbolAddress((void**)&gV,  g_V);

    const int qkSmem = (2*128*TSA + 2*64*TSA) * 4;         // 104448 B
    const int bfSmem = (2*128*TS3 + 2*64*TS3) * 4;         // 55296 B
    const int avSmem = (2*128*TS3 + 2*32*TSV) * 4;         // 55296 B
    cudaFuncSetAttribute(projqk_tf32d_kernel,
        cudaFuncAttributeMaxDynamicSharedMemorySize, qkSmem);
    cudaFuncSetAttribute(fused_scores_topk_kernel,
        cudaFuncAttributeMaxDynamicSharedMemorySize, FUSED_SMEM);
    cudaFuncSetAttribute(projv_bf16_kernel,
        cudaFuncAttributeMaxDynamicSharedMemorySize, bfSmem);
    cudaFuncSetAttribute(av_bf16_kernel,
        cudaFuncAttributeMaxDynamicSharedMemorySize, avSmem);
    cudaFuncSetAttribute(outproj_bf16_kernel,
        cudaFuncAttributeMaxDynamicSharedMemorySize, bfSmem);

    dim3 projqkGrid(Dn/64, Mn/128, 2);          // (16, 32, 2) tf32x3 dual-acc
    projqk_tf32d_kernel<<<projqkGrid, 256, qkSmem>>>(query, key, Wq, Wk, bq, bk, gQ, gK);

    dim3 projvGrid(Dn/64, Mn/128);              // (16, 32) bf16x3
    projv_bf16_kernel<<<projvGrid, 256, bfSmem>>>(value, Wv, bv, gV);

    dim3 fusedGrid(Sn/16, BHn);                 // (128, 32) fused scores+topk
    fused_scores_topk_kernel<<<fusedGrid, 512, FUSED_SMEM>>>(attn);

    dim3 avGrid(Sn/128, BHn);                   // (16, 32) bf16x3
    av_bf16_kernel<<<avGrid, 256, avSmem>>>(attn);

    dim3 outGrid(Dn/64, Mn/128);                // (16, 32) bf16x3
    outproj_bf16_kernel<<<outGrid, 256, bfSmem>>>(Wo, bo, out);
}

// round 16
// speedup vs baseline: 1.2003x; 1.2003x over previous
#include <cuda_runtime.h>
#include <cuda_bf16.h>
#include <cstdint>

#define Bn 2
#define Sn 2048
#define Dn 1024
#define Hn 16
#define HDn 64
#define BHn (Bn*Hn)
#define Mn (Bn*Sn)       // 4096
#define KSEL 1024        // top-k count

// ---- scratch (static device allocations; no cudaMalloc allowed) ----
__device__ float g_Q[Bn*Hn*Sn*HDn];   // (b,h,s,hd)
__device__ float g_K[Bn*Hn*Sn*HDn];
__device__ float g_V[Bn*Hn*Sn*HDn];
__device__ float g_AV[Bn*Hn*Sn*HDn];

// order-preserving float->uint key
__device__ __forceinline__ unsigned fkey(float f){
    unsigned uf = __float_as_uint(f);
    return (uf & 0x80000000u) ? ~uf : (uf | 0x80000000u);
}
__device__ __forceinline__ float finv(unsigned k){
    return __uint_as_float((k & 0x80000000u) ? (k & 0x7FFFFFFFu) : ~k);
}

// ---- tf32 helpers ----
__device__ __forceinline__ void tf32split(float x, unsigned &hi, unsigned &lo){
    unsigned h; asm("cvt.rna.tf32.f32 %0, %1;" : "=r"(h) : "f"(x));
    float hf = __uint_as_float(h);
    asm("cvt.rna.tf32.f32 %0, %1;" : "=r"(lo) : "f"(x - hf));
    hi = h;
}
__device__ __forceinline__ void split4(float4 v, uint4 &hi, uint4 &lo){
    tf32split(v.x, hi.x, lo.x);
    tf32split(v.y, hi.y, lo.y);
    tf32split(v.z, hi.z, lo.z);
    tf32split(v.w, hi.w, lo.w);
}
__device__ __forceinline__ void mma_tf32(float* c, const unsigned* a, const unsigned* b){
    asm volatile("mma.sync.aligned.m16n8k8.row.col.f32.tf32.tf32.f32 "
        "{%0,%1,%2,%3}, {%4,%5,%6,%7}, {%8,%9}, {%0,%1,%2,%3};"
        : "+f"(c[0]), "+f"(c[1]), "+f"(c[2]), "+f"(c[3])
        : "r"(a[0]), "r"(a[1]), "r"(a[2]), "r"(a[3]), "r"(b[0]), "r"(b[1]));
}

// ---- bf16x3 helpers (linear-path GEMMs) ----
__device__ __forceinline__ void bf16x2split(float x, float y, unsigned &hi, unsigned &lo){
    __nv_bfloat16 xh = __float2bfloat16_rn(x);
    __nv_bfloat16 yh = __float2bfloat16_rn(y);
    float xr = x - __bfloat162float(xh);
    float yr = y - __bfloat162float(yh);
    __nv_bfloat16 xl = __float2bfloat16_rn(xr);
    __nv_bfloat16 yl = __float2bfloat16_rn(yr);
    hi = (unsigned)__bfloat16_as_ushort(xh) | ((unsigned)__bfloat16_as_ushort(yh) << 16);
    lo = (unsigned)__bfloat16_as_ushort(xl) | ((unsigned)__bfloat16_as_ushort(yl) << 16);
}
__device__ __forceinline__ void mma_bf16(float* c, const unsigned* a, const unsigned* b){
    asm volatile("mma.sync.aligned.m16n8k16.row.col.f32.bf16.bf16.f32 "
        "{%0,%1,%2,%3}, {%4,%5,%6,%7}, {%8,%9}, {%0,%1,%2,%3};"
        : "+f"(c[0]), "+f"(c[1]), "+f"(c[2]), "+f"(c[3])
        : "r"(a[0]), "r"(a[1]), "r"(a[2]), "r"(a[3]), "r"(b[0]), "r"(b[1]));
}

// tile strides (u32 words)
#define TSA 68   // tf32 64-wide row tiles: conflict-free fragment LDS
#define TS3 36   // bf16 32-word row tiles: conflict-free
#define TSV 72   // bf16 av V pair-row tiles: conflict-free

// tf32x3 warp micro (DUAL accumulators) for QK proj
__device__ __forceinline__ void mma_chunk_rowB_dual(
    float accH[2][4][4], float accX[2][4][4],
    const unsigned* Ah, const unsigned* Al,
    const unsigned* Bh, const unsigned* Bl, int mb, int nb, int g, int c)
{
    #pragma unroll
    for (int ks = 0; ks < 8; ks++){
        unsigned ah[2][4], al[2][4];
        #pragma unroll
        for (int mf=0; mf<2; mf++){
            const unsigned* bse = Ah + (mb+mf*16)*TSA + ks*8;
            const unsigned* bsl = Al + (mb+mf*16)*TSA + ks*8;
            ah[mf][0]=bse[ g   *TSA + c  ]; al[mf][0]=bsl[ g   *TSA + c  ];
            ah[mf][1]=bse[(g+8)*TSA + c  ]; al[mf][1]=bsl[(g+8)*TSA + c  ];
            ah[mf][2]=bse[ g   *TSA + c+4]; al[mf][2]=bsl[ g   *TSA + c+4];
            ah[mf][3]=bse[(g+8)*TSA + c+4]; al[mf][3]=bsl[(g+8)*TSA + c+4];
        }
        #pragma unroll
        for (int nf=0; nf<4; nf++){
            unsigned bh_[2], bl_[2];
            const unsigned* bse = Bh + (nb+nf*8+g)*TSA + ks*8;
            const unsigned* bsl = Bl + (nb+nf*8+g)*TSA + ks*8;
            bh_[0]=bse[c]; bh_[1]=bse[c+4];
            bl_[0]=bsl[c]; bl_[1]=bsl[c+4];
            #pragma unroll
            for (int mf=0; mf<2; mf++){
                mma_tf32(accH[mf][nf], ah[mf], bh_);
                mma_tf32(accX[mf][nf], ah[mf], bl_);
                mma_tf32(accX[mf][nf], al[mf], bh_);
            }
        }
    }
}

// tf32x3 warp micro (single accumulator): scores
__device__ __forceinline__ void mma_chunk_rowB(
    float acc[2][4][4], const unsigned* Ah, const unsigned* Al,
    const unsigned* Bh, const unsigned* Bl, int mb, int nb, int g, int c)
{
    #pragma unroll
    for (int ks = 0; ks < 8; ks++){
        unsigned ah[2][4], al[2][4];
        #pragma unroll
        for (int mf=0; mf<2; mf++){
            const unsigned* bse = Ah + (mb+mf*16)*TSA + ks*8;
            const unsigned* bsl = Al + (mb+mf*16)*TSA + ks*8;
            ah[mf][0]=bse[ g   *TSA + c  ]; al[mf][0]=bsl[ g   *TSA + c  ];
            ah[mf][1]=bse[(g+8)*TSA + c  ]; al[mf][1]=bsl[(g+8)*TSA + c  ];
            ah[mf][2]=bse[ g   *TSA + c+4]; al[mf][2]=bsl[ g   *TSA + c+4];
            ah[mf][3]=bse[(g+8)*TSA + c+4]; al[mf][3]=bsl[(g+8)*TSA + c+4];
        }
        #pragma unroll
        for (int nf=0; nf<4; nf++){
            unsigned bh_[2], bl_[2];
            const unsigned* bse = Bh + (nb+nf*8+g)*TSA + ks*8;
            const unsigned* bsl = Bl + (nb+nf*8+g)*TSA + ks*8;
            bh_[0]=bse[c]; bh_[1]=bse[c+4];
            bl_[0]=bsl[c]; bl_[1]=bsl[c+4];
            #pragma unroll
            for (int mf=0; mf<2; mf++){
                mma_tf32(acc[mf][nf], ah[mf], bh_);
                mma_tf32(acc[mf][nf], ah[mf], bl_);
                mma_tf32(acc[mf][nf], al[mf], bh_);
            }
        }
    }
}

// bf16x3 warp micro: 32m x 32n, one 64-k chunk
__device__ __forceinline__ void mma_chunk_rowB_bf16(
    float acc[2][4][4], const unsigned* Ah, const unsigned* Al,
    const unsigned* Bh, const unsigned* Bl, int mb, int nb, int g, int c)
{
    #pragma unroll
    for (int ks = 0; ks < 4; ks++){
        unsigned ah[2][4], al[2][4];
        #pragma unroll
        for (int mf=0; mf<2; mf++){
            const unsigned* ph = Ah + (mb+mf*16)*TS3 + ks*8;
            const unsigned* pl = Al + (mb+mf*16)*TS3 + ks*8;
            ah[mf][0]=ph[ g   *TS3 + c  ]; al[mf][0]=pl[ g   *TS3 + c  ];
            ah[mf][1]=ph[(g+8)*TS3 + c  ]; al[mf][1]=pl[(g+8)*TS3 + c  ];
            ah[mf][2]=ph[ g   *TS3 + c+4]; al[mf][2]=pl[ g   *TS3 + c+4];
            ah[mf][3]=ph[(g+8)*TS3 + c+4]; al[mf][3]=pl[(g+8)*TS3 + c+4];
        }
        #pragma unroll
        for (int nf=0; nf<4; nf++){
            const unsigned* ph = Bh + (nb+nf*8+g)*TS3 + ks*8;
            const unsigned* pl = Bl + (nb+nf*8+g)*TS3 + ks*8;
            unsigned bh_[2] = { ph[c], ph[c+4] };
            unsigned bl_[2] = { pl[c], pl[c+4] };
            #pragma unroll
            for (int mf=0; mf<2; mf++){
                mma_bf16(acc[mf][nf], ah[mf], bh_);
                mma_bf16(acc[mf][nf], ah[mf], bl_);
                mma_bf16(acc[mf][nf], al[mf], bh_);
            }
        }
    }
}

// ============================================================
// Kernel 1a: Q/K projections via tf32x3 DUAL-ACC MMA (R14 proven)
// ============================================================
__global__ __launch_bounds__(256) void projqk_tf32d_kernel(
    const float* __restrict__ Aq, const float* __restrict__ Ak,
    const float* __restrict__ Wq, const float* __restrict__ Wk,
    const float* __restrict__ bq, const float* __restrict__ bk,
    float* __restrict__ Oq, float* __restrict__ Ok)
{
    const float* A; const float* W; const float* bias; float* Out;
    if (blockIdx.z == 0) { A = Aq; W = Wq; bias = bq; Out = Oq; }
    else                 { A = Ak; W = Wk; bias = bk; Out = Ok; }

    extern __shared__ unsigned sm[];
    unsigned* Ah = sm;
    unsigned* Al = Ah + 128*TSA;
    unsigned* Bh = Al + 128*TSA;
    unsigned* Bl = Bh + 64*TSA;

    int m0 = blockIdx.y * 128;
    int n0 = blockIdx.x * 64;
    int tid = threadIdx.x;
    int lane = tid & 31, w = tid >> 5;
    int mb = (w >> 1) * 32, nb = (w & 1) * 32;
    int g = lane >> 2, c = lane & 3;

    float accH[2][4][4], accX[2][4][4];
    #pragma unroll
    for (int mf=0;mf<2;mf++)
        #pragma unroll
        for (int nf=0;nf<4;nf++)
            #pragma unroll
            for (int e=0;e<4;e++){ accH[mf][nf][e]=0.f; accX[mf][nf][e]=0.f; }

    for (int k0 = 0; k0 < Dn; k0 += 64) {
        #pragma unroll
        for (int i = 0; i < 8; i++){
            int idx = tid + i*256;
            int r = idx >> 4, c4 = idx & 15;
            float4 v = *(const float4*)(A + (size_t)(m0+r)*Dn + k0 + c4*4);
            uint4 hi, lo; split4(v, hi, lo);
            *(uint4*)&Ah[r*TSA + c4*4] = hi;
            *(uint4*)&Al[r*TSA + c4*4] = lo;
        }
        #pragma unroll
        for (int i = 0; i < 4; i++){
            int idx = tid + i*256;
            int r = idx >> 4, c4 = idx & 15;
            float4 v = *(const float4*)(W + (size_t)(n0+r)*Dn + k0 + c4*4);
            uint4 hi, lo; split4(v, hi, lo);
            *(uint4*)&Bh[r*TSA + c4*4] = hi;
            *(uint4*)&Bl[r*TSA + c4*4] = lo;
        }
        __syncthreads();
        mma_chunk_rowB_dual(accH, accX, Ah, Al, Bh, Bl, mb, nb, g, c);
        __syncthreads();
    }

    #pragma unroll
    for (int mf=0; mf<2; mf++){
        #pragma unroll
        for (int nf=0; nf<4; nf++){
            int col = n0 + nb + nf*8 + 2*c;
            int h = col >> 6, hd = col & 63;
            float b0 = bias[col], b1 = bias[col+1];
            #pragma unroll
            for (int rr = 0; rr < 2; rr++){
                int row = m0 + mb + mf*16 + g + rr*8;
                int b = row / Sn, s = row % Sn;
                float2 v = make_float2(
                    (accH[mf][nf][2*rr]   + accX[mf][nf][2*rr])   + b0,
                    (accH[mf][nf][2*rr+1] + accX[mf][nf][2*rr+1]) + b1);
                *(float2*)&Out[(((size_t)(b*Hn + h))*Sn + s)*HDn + hd] = v;
            }
        }
    }
}

// ============================================================
// Kernel 1b: V projection via bf16x3 MMA (R13 proven)
// ============================================================
__global__ __launch_bounds__(256) void projv_bf16_kernel(
    const float* __restrict__ A, const float* __restrict__ W,
    const float* __restrict__ bias, float* __restrict__ Out)
{
    extern __shared__ unsigned sm[];
    unsigned* Ah = sm;
    unsigned* Al = Ah + 128*TS3;
    unsigned* Bh = Al + 128*TS3;
    unsigned* Bl = Bh + 64*TS3;

    int m0 = blockIdx.y * 128;
    int n0 = blockIdx.x * 64;
    int tid = threadIdx.x;
    int lane = tid & 31, w = tid >> 5;
    int mb = (w >> 1) * 32, nb = (w & 1) * 32;
    int g = lane >> 2, c = lane & 3;

    float acc[2][4][4];
    #pragma unroll
    for (int mf=0;mf<2;mf++)
        #pragma unroll
        for (int nf=0;nf<4;nf++)
            #pragma unroll
            for (int e=0;e<4;e++) acc[mf][nf][e]=0.f;

    for (int k0 = 0; k0 < Dn; k0 += 64) {
        #pragma unroll
        for (int i = 0; i < 8; i++){
            int idx = tid + i*256;
            int r = idx >> 4, c4 = idx & 15;
            float4 v = *(const float4*)(A + (size_t)(m0+r)*Dn + k0 + c4*4);
            unsigned h0,l0,h1,l1;
            bf16x2split(v.x, v.y, h0, l0);
            bf16x2split(v.z, v.w, h1, l1);
            *(uint2*)&Ah[r*TS3 + c4*2] = make_uint2(h0, h1);
            *(uint2*)&Al[r*TS3 + c4*2] = make_uint2(l0, l1);
        }
        #pragma unroll
        for (int i = 0; i < 4; i++){
            int idx = tid + i*256;
            int r = idx >> 4, c4 = idx & 15;
            float4 v = *(const float4*)(W + (size_t)(n0+r)*Dn + k0 + c4*4);
            unsigned h0,l0,h1,l1;
            bf16x2split(v.x, v.y, h0, l0);
            bf16x2split(v.z, v.w, h1, l1);
            *(uint2*)&Bh[r*TS3 + c4*2] = make_uint2(h0, h1);
            *(uint2*)&Bl[r*TS3 + c4*2] = make_uint2(l0, l1);
        }
        __syncthreads();
        mma_chunk_rowB_bf16(acc, Ah, Al, Bh, Bl, mb, nb, g, c);
        __syncthreads();
    }

    #pragma unroll
    for (int mf=0; mf<2; mf++){
        #pragma unroll
        for (int nf=0; nf<4; nf++){
            int col = n0 + nb + nf*8 + 2*c;
            int h = col >> 6, hd = col & 63;
            float b0 = bias[col], b1 = bias[col+1];
            #pragma unroll
            for (int rr = 0; rr < 2; rr++){
                int row = m0 + mb + mf*16 + g + rr*8;
                int b = row / Sn, s = row % Sn;
                float2 v = make_float2(acc[mf][nf][2*rr] + b0, acc[mf][nf][2*rr+1] + b1);
                *(float2*)&Out[(((size_t)(b*Hn + h))*Sn + s)*HDn + hd] = v;
            }
        }
    }
}

// ============================================================
// Kernel 2: scores via tf32x3 MMA (R11/R14 proven — unchanged)
// ============================================================
__global__ __launch_bounds__(256) void scores_mma_kernel(float* __restrict__ attn)
{
    extern __shared__ unsigned sm[];
    unsigned* Ah = sm;
    unsigned* Al = Ah + 128*TSA;
    unsigned* Bh = Al + 128*TSA;
    unsigned* Bl = Bh + 64*TSA;

    int bh = blockIdx.z;
    int q0 = blockIdx.y * 128;
    int n0 = blockIdx.x * 64;
    const float* Qb = g_Q + (size_t)bh*Sn*HDn;
    const float* Kb = g_K + (size_t)bh*Sn*HDn;
    float* Cb = attn + (size_t)bh*Sn*Sn;
    int tid = threadIdx.x;
    int lane = tid & 31, w = tid >> 5;
    int mb = (w >> 1) * 32, nb = (w & 1) * 32;
    int g = lane >> 2, c = lane & 3;

    #pragma unroll
    for (int i = 0; i < 8; i++){
        int idx = tid + i*256;
        int r = idx >> 4, c4 = idx & 15;
        float4 v = *(const float4*)(Qb + (size_t)(q0+r)*HDn + c4*4);
        uint4 hi, lo; split4(v, hi, lo);
        *(uint4*)&Ah[r*TSA + c4*4] = hi;
        *(uint4*)&Al[r*TSA + c4*4] = lo;
    }
    #pragma unroll
    for (int i = 0; i < 4; i++){
        int idx = tid + i*256;
        int r = idx >> 4, c4 = idx & 15;
        float4 v = *(const float4*)(Kb + (size_t)(n0+r)*HDn + c4*4);
        uint4 hi, lo; split4(v, hi, lo);
        *(uint4*)&Bh[r*TSA + c4*4] = hi;
        *(uint4*)&Bl[r*TSA + c4*4] = lo;
    }
    __syncthreads();

    float acc[2][4][4];
    #pragma unroll
    for (int mf=0;mf<2;mf++)
        #pragma unroll
        for (int nf=0;nf<4;nf++)
            #pragma unroll
            for (int e=0;e<4;e++) acc[mf][nf][e]=0.f;

    mma_chunk_rowB(acc, Ah, Al, Bh, Bl, mb, nb, g, c);

    const float scale = 0.125f;
    #pragma unroll
    for (int mf=0; mf<2; mf++){
        #pragma unroll
        for (int nf=0; nf<4; nf++){
            int col = n0 + nb + nf*8 + 2*c;
            #pragma unroll
            for (int rr = 0; rr < 2; rr++){
                int row = q0 + mb + mf*16 + g + rr*8;
                float2 v = make_float2(acc[mf][nf][2*rr]*scale, acc[mf][nf][2*rr+1]*scale);
                *(float2*)(Cb + (size_t)row*Sn + col) = v;
            }
        }
    }
}

// ============================================================
// Kernel 3: per-WARP exact top-k + softmax, 5 radix passes (7,7,6,6,6).
// Lane-private u16 histograms, region stride 65 words (conflict-free:
// insert bank (lane+word)%32; reduce bank (l+w)%32). Threshold semantics
// identical to R8/R14 (exact k-th largest key, ties kept).
// ============================================================
#define TKW 8
#define HWORDS 65
#define TOPK_SMEM (TKW*32*HWORDS*4)
__global__ __launch_bounds__(256) void topk_softmax_kernel(float* __restrict__ attn)
{
    extern __shared__ unsigned histsm[];

    const int tid  = threadIdx.x;
    const int lane = tid & 31;
    const int w    = tid >> 5;
    const size_t row = (size_t)blockIdx.x * TKW + w;
    float* rowp = attn + row * (size_t)Sn;
    unsigned* H = histsm + w*(32*HWORDS);

    unsigned ku[64];
    #pragma unroll
    for (int j = 0; j < 16; j++) {
        float4 v = *(const float4*)(rowp + lane*4 + j*128);
        ku[j*4+0]=fkey(v.x); ku[j*4+1]=fkey(v.y); ku[j*4+2]=fkey(v.z); ku[j*4+3]=fkey(v.w);
    }
    unsigned kmax = 0u;
    #pragma unroll
    for (int e = 0; e < 64; e++) kmax = max(kmax, ku[e]);
    #pragma unroll
    for (int o=16;o>0;o>>=1) kmax = max(kmax, __shfl_xor_sync(0xffffffffu, kmax, o));
    float gmax = finv(kmax);

    unsigned prefix = 0u;
    int r = KSEL;
    #pragma unroll 1
    for (int p = 0; p < 5; p++) {
        const int shift = (p < 2) ? (25 - 7*p) : (12 - 6*(p-2));   // 25,18,12,6,0
        const int nbit  = (p < 2) ? 7 : 6;
        const unsigned binmask = (1u << nbit) - 1u;
        const int sh2 = shift + nbit;                              // 32,25,18,12,6
        const unsigned hm = (sh2 >= 32) ? 0u : (0xFFFFFFFFu << sh2);
        const int nzero = (nbit == 7) ? 65 : 33;

        unsigned* reg = H + lane*HWORDS;
        for (int i = 0; i < nzero; i++) reg[i] = 0u;
        __syncwarp();
        #pragma unroll
        for (int e = 0; e < 64; e++) {
            unsigned u = ku[e];
            if ((u & hm) == prefix) {
                unsigned b = (u >> shift) & binmask;
                atomicAdd(&H[lane*HWORDS + (b >> 1)], 1u << (16*(b & 1)));
            }
        }
        __syncwarp();

        int found = -1, rnew = 0;
        if (nbit == 7) {
            // lane owns bins 4*lane .. 4*lane+3 (words 2*lane, 2*lane+1)
            unsigned a0 = 0u, a1 = 0u;
            #pragma unroll
            for (int l = 0; l < 32; l++){
                a0 += H[l*HWORDS + 2*lane];
                a1 += H[l*HWORDS + 2*lane + 1];
            }
            int c0 = (int)(a0 & 0xFFFFu), c1 = (int)(a0 >> 16);
            int c2 = (int)(a1 & 0xFFFFu), c3 = (int)(a1 >> 16);
            int s = c0 + c1 + c2 + c3;
            int suf = s;
            #pragma unroll
            for (int o = 1; o < 32; o <<= 1) {
                int v = __shfl_down_sync(0xffffffffu, suf, o);
                if (lane + o < 32) suf += v;
            }
            int ge1 = suf - c0;
            int ge2 = ge1 - c1;
            int ge3 = ge2 - c2;
            int geN = ge3 - c3;
            if (ge3 >= r && geN < r){ found = 4*lane + 3; rnew = r - geN; }
            if (ge2 >= r && ge3 < r){ found = 4*lane + 2; rnew = r - ge3; }
            if (ge1 >= r && ge2 < r){ found = 4*lane + 1; rnew = r - ge2; }
            if (suf >= r && ge1 < r){ found = 4*lane;     rnew = r - ge1; }
        } else {
            // lane owns bins 2*lane, 2*lane+1 (word lane)
            unsigned acc = 0u;
            #pragma unroll
            for (int l = 0; l < 32; l++) acc += H[l*HWORDS + lane];
            int cLo = (int)(acc & 0xFFFFu);
            int cHi = (int)(acc >> 16);
            int s   = cLo + cHi;
            int suf = s;
            #pragma unroll
            for (int o = 1; o < 32; o <<= 1) {
                int v = __shfl_down_sync(0xffffffffu, suf, o);
                if (lane + o < 32) suf += v;
            }
            int geH = suf - cLo;
            int geN = suf - s;
            if (geH >= r && geN < r) { found = 2*lane + 1; rnew = r - geN; }
            if (suf >= r && geH < r) { found = 2*lane;     rnew = r - geH; }
        }
        unsigned ball = __ballot_sync(0xffffffffu, found >= 0);
        int src = __ffs(ball) - 1;
        unsigned bsel = __shfl_sync(0xffffffffu, (unsigned)found, src);
        r = __shfl_sync(0xffffffffu, rnew, src);
        prefix |= (bsel << shift);
        __syncwarp();
    }
    unsigned thr = prefix;

    float lsumf = 0.f;
    #pragma unroll
    for (int e = 0; e < 64; e++) {
        unsigned k = ku[e];
        float ex = 0.f;
        if (k >= thr) ex = __expf(finv(k) - gmax);
        ku[e] = __float_as_uint(ex);
        lsumf += ex;
    }
    #pragma unroll
    for (int o=16;o>0;o>>=1) lsumf += __shfl_xor_sync(0xffffffffu, lsumf, o);
    float inv = 1.f / lsumf;
    #pragma unroll
    for (int j = 0; j < 16; j++) {
        float4 v = make_float4(__uint_as_float(ku[j*4+0])*inv,
                               __uint_as_float(ku[j*4+1])*inv,
                               __uint_as_float(ku[j*4+2])*inv,
                               __uint_as_float(ku[j*4+3])*inv);
        *(float4*)(rowp + lane*4 + j*128) = v;
    }
}

// ============================================================
// Kernel 4: AV via bf16x3 MMA, DOUBLE-BUFFERED (arithmetic identical to R13/R14)
// ============================================================
#define AVBUF (2*128*TS3 + 2*32*TSV)     // words per buffer
__global__ __launch_bounds__(256, 2) void av_bf16_kernel(const float* __restrict__ attn)
{
    extern __shared__ unsigned sm[];

    int bh = blockIdx.y;
    int m0 = blockIdx.x * 128;
    const float* Ab = attn + (size_t)bh*Sn*Sn;
    const float* Vb = g_V + (size_t)bh*Sn*HDn;
    float* Cb = g_AV + (size_t)bh*Sn*HDn;
    int tid = threadIdx.x;
    int lane = tid & 31, w = tid >> 5;
    int mb = (w >> 1) * 32, nb = (w & 1) * 32;
    int g = lane >> 2, c = lane & 3;

    float acc[2][4][4];
    #pragma unroll
    for (int mf=0;mf<2;mf++)
        #pragma unroll
        for (int nf=0;nf<4;nf++)
            #pragma unroll
            for (int e=0;e<4;e++) acc[mf][nf][e]=0.f;

    // chunk loader (global -> split -> smem buffer)
    auto load_chunk = [&](int k0, unsigned* buf){
        unsigned* Ah = buf;
        unsigned* Al = Ah + 128*TS3;
        unsigned* Vh = Al + 128*TS3;
        unsigned* Vl = Vh + 32*TSV;
        #pragma unroll
        for (int i = 0; i < 8; i++){
            int idx = tid + i*256;
            int r = idx >> 4, c4 = idx & 15;
            float4 v = *(const float4*)(Ab + (size_t)(m0+r)*Sn + k0 + c4*4);
            unsigned h0,l0,h1,l1;
            bf16x2split(v.x, v.y, h0, l0);
            bf16x2split(v.z, v.w, h1, l1);
            *(uint2*)&Ah[r*TS3 + c4*2] = make_uint2(h0, h1);
            *(uint2*)&Al[r*TS3 + c4*2] = make_uint2(l0, l1);
        }
        #pragma unroll
        for (int i = 0; i < 2; i++){
            int idx = tid + i*256;
            int pr = idx >> 4, c4 = idx & 15;
            int d = c4 * 4;
            float4 v0 = *(const float4*)(Vb + (size_t)(k0 + 2*pr    )*HDn + d);
            float4 v1 = *(const float4*)(Vb + (size_t)(k0 + 2*pr + 1)*HDn + d);
            unsigned h, l;
            bf16x2split(v0.x, v1.x, h, l); Vh[pr*TSV + d + 0] = h; Vl[pr*TSV + d + 0] = l;
            bf16x2split(v0.y, v1.y, h, l); Vh[pr*TSV + d + 1] = h; Vl[pr*TSV + d + 1] = l;
            bf16x2split(v0.z, v1.z, h, l); Vh[pr*TSV + d + 2] = h; Vl[pr*TSV + d + 2] = l;
            bf16x2split(v0.w, v1.w, h, l); Vh[pr*TSV + d + 3] = h; Vl[pr*TSV + d + 3] = l;
        }
    };

    load_chunk(0, sm);
    __syncthreads();

    for (int ci = 0; ci < 32; ci++){
        unsigned* buf = sm + (ci & 1)*AVBUF;
        if (ci + 1 < 32)
            load_chunk((ci + 1)*64, sm + ((ci + 1) & 1)*AVBUF);

        unsigned* Ah = buf;
        unsigned* Al = Ah + 128*TS3;
        unsigned* Vh = Al + 128*TS3;
        unsigned* Vl = Vh + 32*TSV;
        #pragma unroll
        for (int ks = 0; ks < 4; ks++){
            unsigned ah[2][4], al[2][4];
            #pragma unroll
            for (int mf=0; mf<2; mf++){
                const unsigned* ph = Ah + (mb+mf*16)*TS3 + ks*8;
                const unsigned* pl = Al + (mb+mf*16)*TS3 + ks*8;
                ah[mf][0]=ph[ g   *TS3 + c  ]; al[mf][0]=pl[ g   *TS3 + c  ];
                ah[mf][1]=ph[(g+8)*TS3 + c  ]; al[mf][1]=pl[(g+8)*TS3 + c  ];
                ah[mf][2]=ph[ g   *TS3 + c+4]; al[mf][2]=pl[ g   *TS3 + c+4];
                ah[mf][3]=ph[(g+8)*TS3 + c+4]; al[mf][3]=pl[(g+8)*TS3 + c+4];
            }
            #pragma unroll
            for (int nf=0; nf<4; nf++){
                int d = nb + nf*8 + g;
                unsigned bh_[2], bl_[2];
                bh_[0]=Vh[(ks*8 + c    )*TSV + d]; bl_[0]=Vl[(ks*8 + c    )*TSV + d];
                bh_[1]=Vh[(ks*8 + c + 4)*TSV + d]; bl_[1]=Vl[(ks*8 + c + 4)*TSV + d];
                #pragma unroll
                for (int mf=0; mf<2; mf++){
                    mma_bf16(acc[mf][nf], ah[mf], bh_);
                    mma_bf16(acc[mf][nf], ah[mf], bl_);
                    mma_bf16(acc[mf][nf], al[mf], bh_);
                }
            }
        }
        __syncthreads();
    }

    #pragma unroll
    for (int mf=0; mf<2; mf++){
        #pragma unroll
        for (int nf=0; nf<4; nf++){
            int col = nb + nf*8 + 2*c;
            #pragma unroll
            for (int rr = 0; rr < 2; rr++){
                int row = m0 + mb + mf*16 + g + rr*8;
                float2 v = make_float2(acc[mf][nf][2*rr], acc[mf][nf][2*rr+1]);
                *(float2*)(Cb + (size_t)row*HDn + col) = v;
            }
        }
    }
}

// ============================================================
// Kernel 5: out projection via bf16x3 MMA (R13 proven)
// ============================================================
__global__ __launch_bounds__(256) void outproj_bf16_kernel(
    const float* __restrict__ Wo, const float* __restrict__ bo,
    float* __restrict__ out)
{
    extern __shared__ unsigned sm[];
    unsigned* Ah = sm;
    unsigned* Al = Ah + 128*TS3;
    unsigned* Bh = Al + 128*TS3;
    unsigned* Bl = Bh + 64*TS3;

    int m0 = blockIdx.y * 128;
    int n0 = blockIdx.x * 64;
    int tid = threadIdx.x;
    int lane = tid & 31, w = tid >> 5;
    int mb = (w >> 1) * 32, nb = (w & 1) * 32;
    int g = lane >> 2, c = lane & 3;

    float acc[2][4][4];
    #pragma unroll
    for (int mf=0;mf<2;mf++)
        #pragma unroll
        for (int nf=0;nf<4;nf++)
            #pragma unroll
            for (int e=0;e<4;e++) acc[mf][nf][e]=0.f;

    for (int k0 = 0; k0 < Dn; k0 += 64) {
        int h = k0 >> 6;
        #pragma unroll
        for (int i = 0; i < 8; i++){
            int idx = tid + i*256;
            int r = idx >> 4, c4 = idx & 15;
            int m = m0 + r;
            int b = m / Sn, s = m % Sn;
            float4 v = *(const float4*)(g_AV + (((size_t)(b*Hn + h))*Sn + s)*HDn + c4*4);
            unsigned h0,l0,h1,l1;
            bf16x2split(v.x, v.y, h0, l0);
            bf16x2split(v.z, v.w, h1, l1);
            *(uint2*)&Ah[r*TS3 + c4*2] = make_uint2(h0, h1);
            *(uint2*)&Al[r*TS3 + c4*2] = make_uint2(l0, l1);
        }
        #pragma unroll
        for (int i = 0; i < 4; i++){
            int idx = tid + i*256;
            int r = idx >> 4, c4 = idx & 15;
            float4 v = *(const float4*)(Wo + (size_t)(n0+r)*Dn + k0 + c4*4);
            unsigned h0,l0,h1,l1;
            bf16x2split(v.x, v.y, h0, l0);
            bf16x2split(v.z, v.w, h1, l1);
            *(uint2*)&Bh[r*TS3 + c4*2] = make_uint2(h0, h1);
            *(uint2*)&Bl[r*TS3 + c4*2] = make_uint2(l0, l1);
        }
        __syncthreads();
        mma_chunk_rowB_bf16(acc, Ah, Al, Bh, Bl, mb, nb, g, c);
        __syncthreads();
    }

    #pragma unroll
    for (int mf=0; mf<2; mf++){
        #pragma unroll
        for (int nf=0; nf<4; nf++){
            int col = n0 + nb + nf*8 + 2*c;
            float b0 = bo[col], b1 = bo[col+1];
            #pragma unroll
            for (int rr = 0; rr < 2; rr++){
                int row = m0 + mb + mf*16 + g + rr*8;
                float2 v = make_float2(acc[mf][nf][2*rr] + b0, acc[mf][nf][2*rr+1] + b1);
                *(float2*)(out + (size_t)row*Dn + col) = v;
            }
        }
    }
}

// ============================================================
extern "C" void kernel_launch(void* const* d_in, const int* in_sizes, int n_in,
                              void* d_out, int out_size)
{
    const float* query = (const float*)d_in[0];
    const float* key   = (const float*)d_in[1];
    const float* value = (const float*)d_in[2];
    const float* Wq = (const float*)d_in[3];
    const float* bq = (const float*)d_in[4];
    const float* Wk = (const float*)d_in[5];
    const float* bk = (const float*)d_in[6];
    const float* Wv = (const float*)d_in[7];
    const float* bv = (const float*)d_in[8];
    const float* Wo = (const float*)d_in[9];
    const float* bo = (const float*)d_in[10];

    float* out  = (float*)d_out;
    float* attn = out + (size_t)Bn * Sn * Dn;

    float* gQ;  cudaGetSymbolAddress((void**)&gQ,  g_Q);
    float* gK;  cudaGetSymbolAddress((void**)&gK,  g_K);
    float* gV;  cudaGetSymbolAddress((void**)&gV,  g_V);

    const int qkSmem  = (2*128*TSA + 2*64*TSA) * 4;        // 104448 B
    const int bfSmem  = (2*128*TS3 + 2*64*TS3) * 4;        // 55296 B
    const int avSmem2 = 2 * AVBUF * 4;                     // 110592 B
    cudaFuncSetAttribute(projqk_tf32d_kernel,
        cudaFuncAttributeMaxDynamicSharedMemorySize, qkSmem);
    cudaFuncSetAttribute(scores_mma_kernel,
        cudaFuncAttributeMaxDynamicSharedMemorySize, qkSmem);
    cudaFuncSetAttribute(projv_bf16_kernel,
        cudaFuncAttributeMaxDynamicSharedMemorySize, bfSmem);
    cudaFuncSetAttribute(topk_softmax_kernel,
        cudaFuncAttributeMaxDynamicSharedMemorySize, TOPK_SMEM);
    cudaFuncSetAttribute(av_bf16_kernel,
        cudaFuncAttributeMaxDynamicSharedMemorySize, avSmem2);
    cudaFuncSetAttribute(outproj_bf16_kernel,
        cudaFuncAttributeMaxDynamicSharedMemorySize, bfSmem);

    dim3 projqkGrid(Dn/64, Mn/128, 2);          // (16, 32, 2) tf32x3 dual-acc
    projqk_tf32d_kernel<<<projqkGrid, 256, qkSmem>>>(query, key, Wq, Wk, bq, bk, gQ, gK);

    dim3 projvGrid(Dn/64, Mn/128);              // (16, 32) bf16x3
    projv_bf16_kernel<<<projvGrid, 256, bfSmem>>>(value, Wv, bv, gV);

    dim3 scoreGrid(Sn/64, Sn/128, BHn);         // (32, 16, 32) tf32x3
    scores_mma_kernel<<<scoreGrid, 256, qkSmem>>>(attn);

    topk_softmax_kernel<<<BHn * Sn / TKW, 256, TOPK_SMEM>>>(attn);

    dim3 avGrid(Sn/128, BHn);                   // (16, 32) bf16x3 double-buffered
    av_bf16_kernel<<<avGrid, 256, avSmem2>>>(attn);

    dim3 outGrid(Dn/64, Mn/128);                // (16, 32) bf16x3
    outproj_bf16_kernel<<<outGrid, 256, bfSmem>>>(Wo, bo, out);
}

// round 17
// speedup vs baseline: 1.3442x; 1.1199x over previous
#include <cuda_runtime.h>
#include <cuda_bf16.h>
#include <cstdint>

#define Bn 2
#define Sn 2048
#define Dn 1024
#define Hn 16
#define HDn 64
#define BHn (Bn*Hn)
#define Mn (Bn*Sn)       // 4096
#define KSEL 1024        // top-k count

// ---- scratch (static device allocations; no cudaMalloc allowed) ----
__device__ float g_Q[Bn*Hn*Sn*HDn];   // (b,h,s,hd)
__device__ float g_K[Bn*Hn*Sn*HDn];
__device__ float g_V[Bn*Hn*Sn*HDn];
__device__ float g_AV[Bn*Hn*Sn*HDn];

// order-preserving float->uint key
__device__ __forceinline__ unsigned fkey(float f){
    unsigned uf = __float_as_uint(f);
    return (uf & 0x80000000u) ? ~uf : (uf | 0x80000000u);
}
__device__ __forceinline__ float finv(unsigned k){
    return __uint_as_float((k & 0x80000000u) ? (k & 0x7FFFFFFFu) : ~k);
}

// ---- tf32 helpers ----
__device__ __forceinline__ void tf32split(float x, unsigned &hi, unsigned &lo){
    unsigned h; asm("cvt.rna.tf32.f32 %0, %1;" : "=r"(h) : "f"(x));
    float hf = __uint_as_float(h);
    asm("cvt.rna.tf32.f32 %0, %1;" : "=r"(lo) : "f"(x - hf));
    hi = h;
}
__device__ __forceinline__ void split4(float4 v, uint4 &hi, uint4 &lo){
    tf32split(v.x, hi.x, lo.x);
    tf32split(v.y, hi.y, lo.y);
    tf32split(v.z, hi.z, lo.z);
    tf32split(v.w, hi.w, lo.w);
}
__device__ __forceinline__ void mma_tf32(float* c, const unsigned* a, const unsigned* b){
    asm volatile("mma.sync.aligned.m16n8k8.row.col.f32.tf32.tf32.f32 "
        "{%0,%1,%2,%3}, {%4,%5,%6,%7}, {%8,%9}, {%0,%1,%2,%3};"
        : "+f"(c[0]), "+f"(c[1]), "+f"(c[2]), "+f"(c[3])
        : "r"(a[0]), "r"(a[1]), "r"(a[2]), "r"(a[3]), "r"(b[0]), "r"(b[1]));
}

// ---- bf16x3 helpers (linear-path GEMMs) ----
__device__ __forceinline__ void bf16x2split(float x, float y, unsigned &hi, unsigned &lo){
    __nv_bfloat16 xh = __float2bfloat16_rn(x);
    __nv_bfloat16 yh = __float2bfloat16_rn(y);
    float xr = x - __bfloat162float(xh);
    float yr = y - __bfloat162float(yh);
    __nv_bfloat16 xl = __float2bfloat16_rn(xr);
    __nv_bfloat16 yl = __float2bfloat16_rn(yr);
    hi = (unsigned)__bfloat16_as_ushort(xh) | ((unsigned)__bfloat16_as_ushort(yh) << 16);
    lo = (unsigned)__bfloat16_as_ushort(xl) | ((unsigned)__bfloat16_as_ushort(yl) << 16);
}
__device__ __forceinline__ void mma_bf16(float* c, const unsigned* a, const unsigned* b){
    asm volatile("mma.sync.aligned.m16n8k16.row.col.f32.bf16.bf16.f32 "
        "{%0,%1,%2,%3}, {%4,%5,%6,%7}, {%8,%9}, {%0,%1,%2,%3};"
        : "+f"(c[0]), "+f"(c[1]), "+f"(c[2]), "+f"(c[3])
        : "r"(a[0]), "r"(a[1]), "r"(a[2]), "r"(a[3]), "r"(b[0]), "r"(b[1]));
}

// tile strides (u32 words)
#define TSA 68   // tf32 64-wide row tiles: conflict-free fragment LDS
#define TS3 36   // bf16 32-word row tiles: conflict-free
#define TSV 72   // bf16 av V pair-row tiles: conflict-free

// tf32x3 warp micro (DUAL accumulators) for QK proj
__device__ __forceinline__ void mma_chunk_rowB_dual(
    float accH[2][4][4], float accX[2][4][4],
    const unsigned* Ah, const unsigned* Al,
    const unsigned* Bh, const unsigned* Bl, int mb, int nb, int g, int c)
{
    #pragma unroll
    for (int ks = 0; ks < 8; ks++){
        unsigned ah[2][4], al[2][4];
        #pragma unroll
        for (int mf=0; mf<2; mf++){
            const unsigned* bse = Ah + (mb+mf*16)*TSA + ks*8;
            const unsigned* bsl = Al + (mb+mf*16)*TSA + ks*8;
            ah[mf][0]=bse[ g   *TSA + c  ]; al[mf][0]=bsl[ g   *TSA + c  ];
            ah[mf][1]=bse[(g+8)*TSA + c  ]; al[mf][1]=bsl[(g+8)*TSA + c  ];
            ah[mf][2]=bse[ g   *TSA + c+4]; al[mf][2]=bsl[ g   *TSA + c+4];
            ah[mf][3]=bse[(g+8)*TSA + c+4]; al[mf][3]=bsl[(g+8)*TSA + c+4];
        }
        #pragma unroll
        for (int nf=0; nf<4; nf++){
            unsigned bh_[2], bl_[2];
            const unsigned* bse = Bh + (nb+nf*8+g)*TSA + ks*8;
            const unsigned* bsl = Bl + (nb+nf*8+g)*TSA + ks*8;
            bh_[0]=bse[c]; bh_[1]=bse[c+4];
            bl_[0]=bsl[c]; bl_[1]=bsl[c+4];
            #pragma unroll
            for (int mf=0; mf<2; mf++){
                mma_tf32(accH[mf][nf], ah[mf], bh_);
                mma_tf32(accX[mf][nf], ah[mf], bl_);
                mma_tf32(accX[mf][nf], al[mf], bh_);
            }
        }
    }
}

// tf32x3 warp micro (single accumulator): scores
__device__ __forceinline__ void mma_chunk_rowB(
    float acc[2][4][4], const unsigned* Ah, const unsigned* Al,
    const unsigned* Bh, const unsigned* Bl, int mb, int nb, int g, int c)
{
    #pragma unroll
    for (int ks = 0; ks < 8; ks++){
        unsigned ah[2][4], al[2][4];
        #pragma unroll
        for (int mf=0; mf<2; mf++){
            const unsigned* bse = Ah + (mb+mf*16)*TSA + ks*8;
            const unsigned* bsl = Al + (mb+mf*16)*TSA + ks*8;
            ah[mf][0]=bse[ g   *TSA + c  ]; al[mf][0]=bsl[ g   *TSA + c  ];
            ah[mf][1]=bse[(g+8)*TSA + c  ]; al[mf][1]=bsl[(g+8)*TSA + c  ];
            ah[mf][2]=bse[ g   *TSA + c+4]; al[mf][2]=bsl[ g   *TSA + c+4];
            ah[mf][3]=bse[(g+8)*TSA + c+4]; al[mf][3]=bsl[(g+8)*TSA + c+4];
        }
        #pragma unroll
        for (int nf=0; nf<4; nf++){
            unsigned bh_[2], bl_[2];
            const unsigned* bse = Bh + (nb+nf*8+g)*TSA + ks*8;
            const unsigned* bsl = Bl + (nb+nf*8+g)*TSA + ks*8;
            bh_[0]=bse[c]; bh_[1]=bse[c+4];
            bl_[0]=bsl[c]; bl_[1]=bsl[c+4];
            #pragma unroll
            for (int mf=0; mf<2; mf++){
                mma_tf32(acc[mf][nf], ah[mf], bh_);
                mma_tf32(acc[mf][nf], ah[mf], bl_);
                mma_tf32(acc[mf][nf], al[mf], bh_);
            }
        }
    }
}

// bf16x3 warp micro: 32m x 32n, one 64-k chunk
__device__ __forceinline__ void mma_chunk_rowB_bf16(
    float acc[2][4][4], const unsigned* Ah, const unsigned* Al,
    const unsigned* Bh, const unsigned* Bl, int mb, int nb, int g, int c)
{
    #pragma unroll
    for (int ks = 0; ks < 4; ks++){
        unsigned ah[2][4], al[2][4];
        #pragma unroll
        for (int mf=0; mf<2; mf++){
            const unsigned* ph = Ah + (mb+mf*16)*TS3 + ks*8;
            const unsigned* pl = Al + (mb+mf*16)*TS3 + ks*8;
            ah[mf][0]=ph[ g   *TS3 + c  ]; al[mf][0]=pl[ g   *TS3 + c  ];
            ah[mf][1]=ph[(g+8)*TS3 + c  ]; al[mf][1]=pl[(g+8)*TS3 + c  ];
            ah[mf][2]=ph[ g   *TS3 + c+4]; al[mf][2]=pl[ g   *TS3 + c+4];
            ah[mf][3]=ph[(g+8)*TS3 + c+4]; al[mf][3]=pl[(g+8)*TS3 + c+4];
        }
        #pragma unroll
        for (int nf=0; nf<4; nf++){
            const unsigned* ph = Bh + (nb+nf*8+g)*TS3 + ks*8;
            const unsigned* pl = Bl + (nb+nf*8+g)*TS3 + ks*8;
            unsigned bh_[2] = { ph[c], ph[c+4] };
            unsigned bl_[2] = { pl[c], pl[c+4] };
            #pragma unroll
            for (int mf=0; mf<2; mf++){
                mma_bf16(acc[mf][nf], ah[mf], bh_);
                mma_bf16(acc[mf][nf], ah[mf], bl_);
                mma_bf16(acc[mf][nf], al[mf], bh_);
            }
        }
    }
}

// ============================================================
// Kernel 1: MERGED projections. blockIdx.z: 0=Q, 1=K (tf32x3 dual-acc,
// R14-proven), 2=V (bf16x3, R13-proven). Block-uniform branch; both
// paths' arithmetic is bit-identical to the R14 kernels.
// ============================================================
__global__ __launch_bounds__(256) void proj_all_kernel(
    const float* __restrict__ Aq, const float* __restrict__ Ak, const float* __restrict__ Av,
    const float* __restrict__ Wq, const float* __restrict__ Wk, const float* __restrict__ Wv,
    const float* __restrict__ bq, const float* __restrict__ bk, const float* __restrict__ bv,
    float* __restrict__ Oq, float* __restrict__ Ok, float* __restrict__ Ov)
{
    extern __shared__ unsigned sm[];
    int m0 = blockIdx.y * 128;
    int n0 = blockIdx.x * 64;
    int tid = threadIdx.x;
    int lane = tid & 31, w = tid >> 5;
    int mb = (w >> 1) * 32, nb = (w & 1) * 32;
    int g = lane >> 2, c = lane & 3;

    if (blockIdx.z < 2) {
        // ---------- tf32x3 dual-acc path (Q or K) ----------
        const float* A; const float* W; const float* bias; float* Out;
        if (blockIdx.z == 0) { A = Aq; W = Wq; bias = bq; Out = Oq; }
        else                 { A = Ak; W = Wk; bias = bk; Out = Ok; }

        unsigned* Ah = sm;
        unsigned* Al = Ah + 128*TSA;
        unsigned* Bh = Al + 128*TSA;
        unsigned* Bl = Bh + 64*TSA;

        float accH[2][4][4], accX[2][4][4];
        #pragma unroll
        for (int mf=0;mf<2;mf++)
            #pragma unroll
            for (int nf=0;nf<4;nf++)
                #pragma unroll
                for (int e=0;e<4;e++){ accH[mf][nf][e]=0.f; accX[mf][nf][e]=0.f; }

        for (int k0 = 0; k0 < Dn; k0 += 64) {
            #pragma unroll
            for (int i = 0; i < 8; i++){
                int idx = tid + i*256;
                int r = idx >> 4, c4 = idx & 15;
                float4 v = *(const float4*)(A + (size_t)(m0+r)*Dn + k0 + c4*4);
                uint4 hi, lo; split4(v, hi, lo);
                *(uint4*)&Ah[r*TSA + c4*4] = hi;
                *(uint4*)&Al[r*TSA + c4*4] = lo;
            }
            #pragma unroll
            for (int i = 0; i < 4; i++){
                int idx = tid + i*256;
                int r = idx >> 4, c4 = idx & 15;
                float4 v = *(const float4*)(W + (size_t)(n0+r)*Dn + k0 + c4*4);
                uint4 hi, lo; split4(v, hi, lo);
                *(uint4*)&Bh[r*TSA + c4*4] = hi;
                *(uint4*)&Bl[r*TSA + c4*4] = lo;
            }
            __syncthreads();
            mma_chunk_rowB_dual(accH, accX, Ah, Al, Bh, Bl, mb, nb, g, c);
            __syncthreads();
        }

        #pragma unroll
        for (int mf=0; mf<2; mf++){
            #pragma unroll
            for (int nf=0; nf<4; nf++){
                int col = n0 + nb + nf*8 + 2*c;
                int h = col >> 6, hd = col & 63;
                float b0 = bias[col], b1 = bias[col+1];
                #pragma unroll
                for (int rr = 0; rr < 2; rr++){
                    int row = m0 + mb + mf*16 + g + rr*8;
                    int b = row / Sn, s = row % Sn;
                    float2 v = make_float2(
                        (accH[mf][nf][2*rr]   + accX[mf][nf][2*rr])   + b0,
                        (accH[mf][nf][2*rr+1] + accX[mf][nf][2*rr+1]) + b1);
                    *(float2*)&Out[(((size_t)(b*Hn + h))*Sn + s)*HDn + hd] = v;
                }
            }
        }
    } else {
        // ---------- bf16x3 path (V) ----------
        const float* A = Av; const float* W = Wv; const float* bias = bv; float* Out = Ov;
        unsigned* Ah = sm;
        unsigned* Al = Ah + 128*TS3;
        unsigned* Bh = Al + 128*TS3;
        unsigned* Bl = Bh + 64*TS3;

        float acc[2][4][4];
        #pragma unroll
        for (int mf=0;mf<2;mf++)
            #pragma unroll
            for (int nf=0;nf<4;nf++)
                #pragma unroll
                for (int e=0;e<4;e++) acc[mf][nf][e]=0.f;

        for (int k0 = 0; k0 < Dn; k0 += 64) {
            #pragma unroll
            for (int i = 0; i < 8; i++){
                int idx = tid + i*256;
                int r = idx >> 4, c4 = idx & 15;
                float4 v = *(const float4*)(A + (size_t)(m0+r)*Dn + k0 + c4*4);
                unsigned h0,l0,h1,l1;
                bf16x2split(v.x, v.y, h0, l0);
                bf16x2split(v.z, v.w, h1, l1);
                *(uint2*)&Ah[r*TS3 + c4*2] = make_uint2(h0, h1);
                *(uint2*)&Al[r*TS3 + c4*2] = make_uint2(l0, l1);
            }
            #pragma unroll
            for (int i = 0; i < 4; i++){
                int idx = tid + i*256;
                int r = idx >> 4, c4 = idx & 15;
                float4 v = *(const float4*)(W + (size_t)(n0+r)*Dn + k0 + c4*4);
                unsigned h0,l0,h1,l1;
                bf16x2split(v.x, v.y, h0, l0);
                bf16x2split(v.z, v.w, h1, l1);
                *(uint2*)&Bh[r*TS3 + c4*2] = make_uint2(h0, h1);
                *(uint2*)&Bl[r*TS3 + c4*2] = make_uint2(l0, l1);
            }
            __syncthreads();
            mma_chunk_rowB_bf16(acc, Ah, Al, Bh, Bl, mb, nb, g, c);
            __syncthreads();
        }

        #pragma unroll
        for (int mf=0; mf<2; mf++){
            #pragma unroll
            for (int nf=0; nf<4; nf++){
                int col = n0 + nb + nf*8 + 2*c;
                int h = col >> 6, hd = col & 63;
                float b0 = bias[col], b1 = bias[col+1];
                #pragma unroll
                for (int rr = 0; rr < 2; rr++){
                    int row = m0 + mb + mf*16 + g + rr*8;
                    int b = row / Sn, s = row % Sn;
                    float2 v = make_float2(acc[mf][nf][2*rr] + b0, acc[mf][nf][2*rr+1] + b1);
                    *(float2*)&Out[(((size_t)(b*Hn + h))*Sn + s)*HDn + hd] = v;
                }
            }
        }
    }
}

// ============================================================
// Kernel 2: scores via tf32x3 MMA (R11/R14 proven — unchanged)
// ============================================================
__global__ __launch_bounds__(256) void scores_mma_kernel(float* __restrict__ attn)
{
    extern __shared__ unsigned sm[];
    unsigned* Ah = sm;
    unsigned* Al = Ah + 128*TSA;
    unsigned* Bh = Al + 128*TSA;
    unsigned* Bl = Bh + 64*TSA;

    int bh = blockIdx.z;
    int q0 = blockIdx.y * 128;
    int n0 = blockIdx.x * 64;
    const float* Qb = g_Q + (size_t)bh*Sn*HDn;
    const float* Kb = g_K + (size_t)bh*Sn*HDn;
    float* Cb = attn + (size_t)bh*Sn*Sn;
    int tid = threadIdx.x;
    int lane = tid & 31, w = tid >> 5;
    int mb = (w >> 1) * 32, nb = (w & 1) * 32;
    int g = lane >> 2, c = lane & 3;

    #pragma unroll
    for (int i = 0; i < 8; i++){
        int idx = tid + i*256;
        int r = idx >> 4, c4 = idx & 15;
        float4 v = *(const float4*)(Qb + (size_t)(q0+r)*HDn + c4*4);
        uint4 hi, lo; split4(v, hi, lo);
        *(uint4*)&Ah[r*TSA + c4*4] = hi;
        *(uint4*)&Al[r*TSA + c4*4] = lo;
    }
    #pragma unroll
    for (int i = 0; i < 4; i++){
        int idx = tid + i*256;
        int r = idx >> 4, c4 = idx & 15;
        float4 v = *(const float4*)(Kb + (size_t)(n0+r)*HDn + c4*4);
        uint4 hi, lo; split4(v, hi, lo);
        *(uint4*)&Bh[r*TSA + c4*4] = hi;
        *(uint4*)&Bl[r*TSA + c4*4] = lo;
    }
    __syncthreads();

    float acc[2][4][4];
    #pragma unroll
    for (int mf=0;mf<2;mf++)
        #pragma unroll
        for (int nf=0;nf<4;nf++)
            #pragma unroll
            for (int e=0;e<4;e++) acc[mf][nf][e]=0.f;

    mma_chunk_rowB(acc, Ah, Al, Bh, Bl, mb, nb, g, c);

    const float scale = 0.125f;
    #pragma unroll
    for (int mf=0; mf<2; mf++){
        #pragma unroll
        for (int nf=0; nf<4; nf++){
            int col = n0 + nb + nf*8 + 2*c;
            #pragma unroll
            for (int rr = 0; rr < 2; rr++){
                int row = q0 + mb + mf*16 + g + rr*8;
                float2 v = make_float2(acc[mf][nf][2*rr]*scale, acc[mf][nf][2*rr+1]*scale);
                *(float2*)(Cb + (size_t)row*Sn + col) = v;
            }
        }
    }
}

// ============================================================
// Kernel 3: per-WARP exact top-k + softmax (R8/R14 proven form)
// ============================================================
#define TKW 8
__global__ __launch_bounds__(256) void topk_softmax_kernel(float* __restrict__ attn)
{
    __shared__ unsigned hist[TKW][32*33];

    const int tid  = threadIdx.x;
    const int lane = tid & 31;
    const int w    = tid >> 5;
    const size_t row = (size_t)blockIdx.x * TKW + w;
    float* rowp = attn + row * (size_t)Sn;
    unsigned* H = hist[w];

    unsigned ku[64];
    #pragma unroll
    for (int j = 0; j < 16; j++) {
        float4 v = *(const float4*)(rowp + lane*4 + j*128);
        ku[j*4+0]=fkey(v.x); ku[j*4+1]=fkey(v.y); ku[j*4+2]=fkey(v.z); ku[j*4+3]=fkey(v.w);
    }
    unsigned kmax = 0u;
    #pragma unroll
    for (int e = 0; e < 64; e++) kmax = max(kmax, ku[e]);
    #pragma unroll
    for (int o=16;o>0;o>>=1) kmax = max(kmax, __shfl_xor_sync(0xffffffffu, kmax, o));
    float gmax = finv(kmax);

    unsigned prefix = 0u;
    int r = KSEL;
    #pragma unroll 1
    for (int p = 0; p < 6; p++) {
        const int shift = (p < 5) ? (26 - 6*p) : 0;
        const int nbit  = (p < 5) ? 6 : 2;
        const unsigned binmask = (1u << nbit) - 1u;
        const int sh2 = shift + nbit;
        const unsigned hm = (sh2 >= 32) ? 0u : (0xFFFFFFFFu << sh2);

        unsigned* reg = H + lane*33;
        #pragma unroll
        for (int i = 0; i < 33; i++) reg[i] = 0u;
        __syncwarp();
        #pragma unroll
        for (int e = 0; e < 64; e++) {
            unsigned u = ku[e];
            if ((u & hm) == prefix) {
                unsigned b = (u >> shift) & binmask;
                atomicAdd(&H[lane*33 + (b >> 1)], 1u << (16*(b & 1)));
            }
        }
        __syncwarp();
        unsigned acc = 0u;
        #pragma unroll
        for (int l = 0; l < 32; l++) acc += H[l*33 + lane];
        int cLo = (int)(acc & 0xFFFFu);
        int cHi = (int)(acc >> 16);
        int s   = cLo + cHi;
        int suf = s;
        #pragma unroll
        for (int o = 1; o < 32; o <<= 1) {
            int v = __shfl_down_sync(0xffffffffu, suf, o);
            if (lane + o < 32) suf += v;
        }
        int geL = suf;
        int geH = suf - cLo;
        int geN = suf - s;
        int found = -1, rnew = 0;
        if (geH >= r && geN < r) { found = 2*lane + 1; rnew = r - geN; }
        if (geL >= r && geH < r) { found = 2*lane;     rnew = r - geH; }
        unsigned ball = __ballot_sync(0xffffffffu, found >= 0);
        int src = __ffs(ball) - 1;
        unsigned bsel = __shfl_sync(0xffffffffu, (unsigned)found, src);
        r = __shfl_sync(0xffffffffu, rnew, src);
        prefix |= (bsel << shift);
        __syncwarp();
    }
    unsigned thr = prefix;

    float lsumf = 0.f;
    #pragma unroll
    for (int e = 0; e < 64; e++) {
        unsigned k = ku[e];
        float ex = 0.f;
        if (k >= thr) ex = __expf(finv(k) - gmax);
        ku[e] = __float_as_uint(ex);
        lsumf += ex;
    }
    #pragma unroll
    for (int o=16;o>0;o>>=1) lsumf += __shfl_xor_sync(0xffffffffu, lsumf, o);
    float inv = 1.f / lsumf;
    #pragma unroll
    for (int j = 0; j < 16; j++) {
        float4 v = make_float4(__uint_as_float(ku[j*4+0])*inv,
                               __uint_as_float(ku[j*4+1])*inv,
                               __uint_as_float(ku[j*4+2])*inv,
                               __uint_as_float(ku[j*4+3])*inv);
        *(float4*)(rowp + lane*4 + j*128) = v;
    }
}

// ============================================================
// Kernel 4: AV via bf16x3 MMA (R13/R14 proven single-buffer form)
// ============================================================
__global__ __launch_bounds__(256) void av_bf16_kernel(const float* __restrict__ attn)
{
    extern __shared__ unsigned sm[];
    unsigned* Ah = sm;
    unsigned* Al = Ah + 128*TS3;
    unsigned* Vh = Al + 128*TS3;
    unsigned* Vl = Vh + 32*TSV;

    int bh = blockIdx.y;
    int m0 = blockIdx.x * 128;
    const float* Ab = attn + (size_t)bh*Sn*Sn;
    const float* Vb = g_V + (size_t)bh*Sn*HDn;
    float* Cb = g_AV + (size_t)bh*Sn*HDn;
    int tid = threadIdx.x;
    int lane = tid & 31, w = tid >> 5;
    int mb = (w >> 1) * 32, nb = (w & 1) * 32;
    int g = lane >> 2, c = lane & 3;

    float acc[2][4][4];
    #pragma unroll
    for (int mf=0;mf<2;mf++)
        #pragma unroll
        for (int nf=0;nf<4;nf++)
            #pragma unroll
            for (int e=0;e<4;e++) acc[mf][nf][e]=0.f;

    for (int k0 = 0; k0 < Sn; k0 += 64) {
        #pragma unroll
        for (int i = 0; i < 8; i++){
            int idx = tid + i*256;
            int r = idx >> 4, c4 = idx & 15;
            float4 v = *(const float4*)(Ab + (size_t)(m0+r)*Sn + k0 + c4*4);
            unsigned h0,l0,h1,l1;
            bf16x2split(v.x, v.y, h0, l0);
            bf16x2split(v.z, v.w, h1, l1);
            *(uint2*)&Ah[r*TS3 + c4*2] = make_uint2(h0, h1);
            *(uint2*)&Al[r*TS3 + c4*2] = make_uint2(l0, l1);
        }
        #pragma unroll
        for (int i = 0; i < 2; i++){
            int idx = tid + i*256;
            int pr = idx >> 4, c4 = idx & 15;
            int d = c4 * 4;
            float4 v0 = *(const float4*)(Vb + (size_t)(k0 + 2*pr    )*HDn + d);
            float4 v1 = *(const float4*)(Vb + (size_t)(k0 + 2*pr + 1)*HDn + d);
            unsigned h, l;
            bf16x2split(v0.x, v1.x, h, l); Vh[pr*TSV + d + 0] = h; Vl[pr*TSV + d + 0] = l;
            bf16x2split(v0.y, v1.y, h, l); Vh[pr*TSV + d + 1] = h; Vl[pr*TSV + d + 1] = l;
            bf16x2split(v0.z, v1.z, h, l); Vh[pr*TSV + d + 2] = h; Vl[pr*TSV + d + 2] = l;
            bf16x2split(v0.w, v1.w, h, l); Vh[pr*TSV + d + 3] = h; Vl[pr*TSV + d + 3] = l;
        }
        __syncthreads();

        #pragma unroll
        for (int ks = 0; ks < 4; ks++){
            unsigned ah[2][4], al[2][4];
            #pragma unroll
            for (int mf=0; mf<2; mf++){
                const unsigned* ph = Ah + (mb+mf*16)*TS3 + ks*8;
                const unsigned* pl = Al + (mb+mf*16)*TS3 + ks*8;
                ah[mf][0]=ph[ g   *TS3 + c  ]; al[mf][0]=pl[ g   *TS3 + c  ];
                ah[mf][1]=ph[(g+8)*TS3 + c  ]; al[mf][1]=pl[(g+8)*TS3 + c  ];
                ah[mf][2]=ph[ g   *TS3 + c+4]; al[mf][2]=pl[ g   *TS3 + c+4];
                ah[mf][3]=ph[(g+8)*TS3 + c+4]; al[mf][3]=pl[(g+8)*TS3 + c+4];
            }
            #pragma unroll
            for (int nf=0; nf<4; nf++){
                int d = nb + nf*8 + g;
                unsigned bh_[2], bl_[2];
                bh_[0]=Vh[(ks*8 + c    )*TSV + d]; bl_[0]=Vl[(ks*8 + c    )*TSV + d];
                bh_[1]=Vh[(ks*8 + c + 4)*TSV + d]; bl_[1]=Vl[(ks*8 + c + 4)*TSV + d];
                #pragma unroll
                for (int mf=0; mf<2; mf++){
                    mma_bf16(acc[mf][nf], ah[mf], bh_);
                    mma_bf16(acc[mf][nf], ah[mf], bl_);
                    mma_bf16(acc[mf][nf], al[mf], bh_);
                }
            }
        }
        __syncthreads();
    }

    #pragma unroll
    for (int mf=0; mf<2; mf++){
        #pragma unroll
        for (int nf=0; nf<4; nf++){
            int col = nb + nf*8 + 2*c;
            #pragma unroll
            for (int rr = 0; rr < 2; rr++){
                int row = m0 + mb + mf*16 + g + rr*8;
                float2 v = make_float2(acc[mf][nf][2*rr], acc[mf][nf][2*rr+1]);
                *(float2*)(Cb + (size_t)row*HDn + col) = v;
            }
        }
    }
}

// ============================================================
// Kernel 5: out projection via bf16x3 MMA (R13/R14 proven)
// ============================================================
__global__ __launch_bounds__(256) void outproj_bf16_kernel(
    const float* __restrict__ Wo, const float* __restrict__ bo,
    float* __restrict__ out)
{
    extern __shared__ unsigned sm[];
    unsigned* Ah = sm;
    unsigned* Al = Ah + 128*TS3;
    unsigned* Bh = Al + 128*TS3;
    unsigned* Bl = Bh + 64*TS3;

    int m0 = blockIdx.y * 128;
    int n0 = blockIdx.x * 64;
    int tid = threadIdx.x;
    int lane = tid & 31, w = tid >> 5;
    int mb = (w >> 1) * 32, nb = (w & 1) * 32;
    int g = lane >> 2, c = lane & 3;

    float acc[2][4][4];
    #pragma unroll
    for (int mf=0;mf<2;mf++)
        #pragma unroll
        for (int nf=0;nf<4;nf++)
            #pragma unroll
            for (int e=0;e<4;e++) acc[mf][nf][e]=0.f;

    for (int k0 = 0; k0 < Dn; k0 += 64) {
        int h = k0 >> 6;
        #pragma unroll
        for (int i = 0; i < 8; i++){
            int idx = tid + i*256;
            int r = idx >> 4, c4 = idx & 15;
            int m = m0 + r;
            int b = m / Sn, s = m % Sn;
            float4 v = *(const float4*)(g_AV + (((size_t)(b*Hn + h))*Sn + s)*HDn + c4*4);
            unsigned h0,l0,h1,l1;
            bf16x2split(v.x, v.y, h0, l0);
            bf16x2split(v.z, v.w, h1, l1);
            *(uint2*)&Ah[r*TS3 + c4*2] = make_uint2(h0, h1);
            *(uint2*)&Al[r*TS3 + c4*2] = make_uint2(l0, l1);
        }
        #pragma unroll
        for (int i = 0; i < 4; i++){
            int idx = tid + i*256;
            int r = idx >> 4, c4 = idx & 15;
            float4 v = *(const float4*)(Wo + (size_t)(n0+r)*Dn + k0 + c4*4);
            unsigned h0,l0,h1,l1;
            bf16x2split(v.x, v.y, h0, l0);
            bf16x2split(v.z, v.w, h1, l1);
            *(uint2*)&Bh[r*TS3 + c4*2] = make_uint2(h0, h1);
            *(uint2*)&Bl[r*TS3 + c4*2] = make_uint2(l0, l1);
        }
        __syncthreads();
        mma_chunk_rowB_bf16(acc, Ah, Al, Bh, Bl, mb, nb, g, c);
        __syncthreads();
    }

    #pragma unroll
    for (int mf=0; mf<2; mf++){
        #pragma unroll
        for (int nf=0; nf<4; nf++){
            int col = n0 + nb + nf*8 + 2*c;
            float b0 = bo[col], b1 = bo[col+1];
            #pragma unroll
            for (int rr = 0; rr < 2; rr++){
                int row = m0 + mb + mf*16 + g + rr*8;
                float2 v = make_float2(acc[mf][nf][2*rr] + b0, acc[mf][nf][2*rr+1] + b1);
                *(float2*)(out + (size_t)row*Dn + col) = v;
            }
        }
    }
}

// ============================================================
extern "C" void kernel_launch(void* const* d_in, const int* in_sizes, int n_in,
                              void* d_out, int out_size)
{
    const float* query = (const float*)d_in[0];
    const float* key   = (const float*)d_in[1];
    const float* value = (const float*)d_in[2];
    const float* Wq = (const float*)d_in[3];
    const float* bq = (const float*)d_in[4];
    const float* Wk = (const float*)d_in[5];
    const float* bk = (const float*)d_in[6];
    const float* Wv = (const float*)d_in[7];
    const float* bv = (const float*)d_in[8];
    const float* Wo = (const float*)d_in[9];
    const float* bo = (const float*)d_in[10];

    float* out  = (float*)d_out;
    float* attn = out + (size_t)Bn * Sn * Dn;

    float* gQ;  cudaGetSymbolAddress((void**)&gQ,  g_Q);
    float* gK;  cudaGetSymbolAddress((void**)&gK,  g_K);
    float* gV;  cudaGetSymbolAddress((void**)&gV,  g_V);

    const int qkSmem = (2*128*TSA + 2*64*TSA) * 4;         // 104448 B
    const int bfSmem = (2*128*TS3 + 2*64*TS3) * 4;         // 55296 B
    const int avSmem = (2*128*TS3 + 2*32*TSV) * 4;         // 55296 B
    cudaFuncSetAttribute(proj_all_kernel,
        cudaFuncAttributeMaxDynamicSharedMemorySize, qkSmem);
    cudaFuncSetAttribute(scores_mma_kernel,
        cudaFuncAttributeMaxDynamicSharedMemorySize, qkSmem);
    cudaFuncSetAttribute(av_bf16_kernel,
        cudaFuncAttributeMaxDynamicSharedMemorySize, avSmem);
    cudaFuncSetAttribute(outproj_bf16_kernel,
        cudaFuncAttributeMaxDynamicSharedMemorySize, bfSmem);

    dim3 projGrid(Dn/64, Mn/128, 3);            // (16, 32, 3) merged Q/K/V
    proj_all_kernel<<<projGrid, 256, qkSmem>>>(query, key, value,
                                               Wq, Wk, Wv, bq, bk, bv,
                                               gQ, gK, gV);

    dim3 scoreGrid(Sn/64, Sn/128, BHn);         // (32, 16, 32) tf32x3
    scores_mma_kernel<<<scoreGrid, 256, qkSmem>>>(attn);

    topk_softmax_kernel<<<BHn * Sn / TKW, 256>>>(attn);

    dim3 avGrid(Sn/128, BHn);                   // (16, 32) bf16x3
    av_bf16_kernel<<<avGrid, 256, avSmem>>>(attn);

    dim3 outGrid(Dn/64, Mn/128);                // (16, 32) bf16x3
    outproj_bf16_kernel<<<outGrid, 256, bfSmem>>>(Wo, bo, out);
}